// round 10
// baseline (speedup 1.0000x reference)
#include <cuda_runtime.h>
#include <cuda_bf16.h>
#include <cstdint>
#include <math.h>

#define BATCH 4
#define SEQ   1024
#define HID   1024
#define NHEAD 16
#define HDIM  64
#define SCALE 0.125f
#define MTOT  (BATCH*SEQ)

// ------------------------- scratch (device globals) -------------------------
__device__ __nv_bfloat16 g_Ahi[MTOT*HID];        // hi/lo split of GEMM A input
__device__ __nv_bfloat16 g_Alo[MTOT*HID];
__device__ __nv_bfloat16 g_Whi[4*HID*HID];       // transposed weights [N][K], 4 slots
__device__ __nv_bfloat16 g_Wlo[4*HID*HID];
// Q/K/V bf16 hi/lo, head-major [b][h][s][d]
__device__ __nv_bfloat16 g_Qhi[MTOT*HID];
__device__ __nv_bfloat16 g_Qlo[MTOT*HID];
__device__ __nv_bfloat16 g_Khi[MTOT*HID];
__device__ __nv_bfloat16 g_Klo[MTOT*HID];
__device__ __nv_bfloat16 g_Vhi[MTOT*HID];
__device__ __nv_bfloat16 g_Vlo[MTOT*HID];
__device__ int   g_nearest[BATCH*SEQ];
__device__ float g_colbias[BATCH*SEQ];

// ------------------------------ PTX helpers ---------------------------------
__device__ __forceinline__ uint32_t smem_u32(const void* p) {
    uint32_t a;
    asm("{ .reg .u64 t; cvta.to.shared.u64 t, %1; cvt.u32.u64 %0, t; }"
        : "=r"(a) : "l"(p));
    return a;
}

__device__ __forceinline__ void cp_async16(uint32_t saddr, const void* gaddr) {
    asm volatile("cp.async.cg.shared.global [%0], [%1], 16;"
                 :: "r"(saddr), "l"(gaddr) : "memory");
}

__device__ __forceinline__ void ldmatrix_x4(uint32_t* r, uint32_t addr) {
    asm volatile("ldmatrix.sync.aligned.m8n8.x4.shared.b16 {%0,%1,%2,%3}, [%4];"
                 : "=r"(r[0]), "=r"(r[1]), "=r"(r[2]), "=r"(r[3]) : "r"(addr));
}

__device__ __forceinline__ void ldmatrix_x4_t(uint32_t* r, uint32_t addr) {
    asm volatile("ldmatrix.sync.aligned.m8n8.x4.trans.shared.b16 {%0,%1,%2,%3}, [%4];"
                 : "=r"(r[0]), "=r"(r[1]), "=r"(r[2]), "=r"(r[3]) : "r"(addr));
}

__device__ __forceinline__ void mma16816(float* d, const uint32_t* a,
                                         uint32_t b0, uint32_t b1) {
    asm volatile(
        "mma.sync.aligned.m16n8k16.row.col.f32.bf16.bf16.f32 "
        "{%0,%1,%2,%3}, {%4,%5,%6,%7}, {%8,%9}, {%0,%1,%2,%3};"
        : "+f"(d[0]), "+f"(d[1]), "+f"(d[2]), "+f"(d[3])
        : "r"(a[0]), "r"(a[1]), "r"(a[2]), "r"(a[3]), "r"(b0), "r"(b1));
}

#define SWZ(x) ((x) ^ (((x) >> 3) & 0x70))

__device__ __forceinline__ uint32_t pack_bf2(float x, float y) {
    __nv_bfloat162 h = __floats2bfloat162_rn(x, y);
    return *(uint32_t*)&h;
}

// ---------------------------------------------------------------------------
// Morphological bias precompute (parallelized: 32 blocks)
// ---------------------------------------------------------------------------
__global__ void bias_kernel(const int* __restrict__ morpho)
{
    int b = blockIdx.x;
    __shared__ int types[SEQ];
    for (int i = threadIdx.x; i < SEQ; i += blockDim.x)
        types[i] = morpho[b*SEQ + i];
    __syncthreads();
    int q = blockIdx.y * 128 + threadIdx.x;
    int best = -1;
    int bestd = 1 << 30;
    for (int j = 0; j < SEQ; j++) {
        if (types[j] == 2) {
            int d = abs(q - j);
            if (d < bestd) { bestd = d; best = j; }
        }
    }
    g_nearest[b*SEQ + q] = best;
    int t = types[q];
    float cb = 0.0f;
    if (t == 0) cb = 0.75f;
    else if (t == 1) cb = 0.36f;
    g_colbias[b*SEQ + q] = cb;
}

// ---------------------------------------------------------------------------
// fp32 -> bf16 hi/lo split (row-major, vectorized by 4)
// ---------------------------------------------------------------------------
__global__ void __launch_bounds__(256) split_kernel(
    const float4* __restrict__ src, __nv_bfloat162* __restrict__ hi,
    __nv_bfloat162* __restrict__ lo)
{
    int i = blockIdx.x * 256 + threadIdx.x;
    float4 v = src[i];
    __nv_bfloat16 h0 = __float2bfloat16(v.x);
    __nv_bfloat16 h1 = __float2bfloat16(v.y);
    __nv_bfloat16 h2 = __float2bfloat16(v.z);
    __nv_bfloat16 h3 = __float2bfloat16(v.w);
    __nv_bfloat162 ha; ha.x = h0; ha.y = h1;
    __nv_bfloat162 hb; hb.x = h2; hb.y = h3;
    hi[2*i] = ha; hi[2*i+1] = hb;
    __nv_bfloat162 la, lb;
    la.x = __float2bfloat16(v.x - __bfloat162float(h0));
    la.y = __float2bfloat16(v.y - __bfloat162float(h1));
    lb.x = __float2bfloat16(v.z - __bfloat162float(h2));
    lb.y = __float2bfloat16(v.w - __bfloat162float(h3));
    lo[2*i] = la; lo[2*i+1] = lb;
}

// ---------------------------------------------------------------------------
// W [K][N] fp32 -> Wt hi/lo [N][K] bf16 (transpose + split), z = weight slot
// ---------------------------------------------------------------------------
__global__ void wtrans_kernel(const float* __restrict__ W0,
                              const float* __restrict__ W1,
                              const float* __restrict__ W2,
                              const float* __restrict__ W3,
                              __nv_bfloat16* __restrict__ hiB,
                              __nv_bfloat16* __restrict__ loB)
{
    int z = blockIdx.z;
    const float* W = (z == 0) ? W0 : (z == 1) ? W1 : (z == 2) ? W2 : W3;
    __nv_bfloat16* hi = hiB + (size_t)z * HID * HID;
    __nv_bfloat16* lo = loB + (size_t)z * HID * HID;

    __shared__ float t[32][33];
    int n0 = blockIdx.x * 32, k0 = blockIdx.y * 32;
    int c = threadIdx.x, r0 = threadIdx.y;        // 32 x 8
#pragma unroll
    for (int i = 0; i < 4; i++)
        t[r0 + 8*i][c] = W[(size_t)(k0 + r0 + 8*i) * HID + n0 + c];
    __syncthreads();
#pragma unroll
    for (int i = 0; i < 4; i++) {
        int rr = r0 + 8*i;
        float v = t[c][rr];
        __nv_bfloat16 h = __float2bfloat16(v);
        hi[(size_t)(n0 + rr) * HID + k0 + c] = h;
        lo[(size_t)(n0 + rr) * HID + k0 + c] =
            __float2bfloat16(v - __bfloat162float(h));
    }
}

// ---------------------------------------------------------------------------
// Fused 3-term GEMM mainloop. K-chunk = 32; each 128B smem row holds
// hi (bytes 0-63) and lo (bytes 64-127) of one tile row. 32 chunks,
// triple-buffered (3 x 32KB), prefetch depth 2.
// Per chunk/warp: 24 ldmatrix, 96 MMAs (Ah*Bh + Ah*Bl + Al*Bh fused).
// ---------------------------------------------------------------------------
__device__ __forceinline__ void gemm_core(
    const __nv_bfloat16* __restrict__ Ahi, const __nv_bfloat16* __restrict__ Alo,
    const __nv_bfloat16* __restrict__ Bhi, const __nv_bfloat16* __restrict__ Blo,
    int bm, int bn, uint32_t sbase, float acc[4][4][4])
{
    const int tid = threadIdx.x;
    const int L = tid & 31;
    const int wid = tid >> 5;
    const int wm = wid >> 2;
    const int wn = wid & 3;

    const int ldrow = tid >> 1;
    const int ldcu  = (tid & 1) * 4;          // segs 0-3 = hi, 4-7 = lo
    const __nv_bfloat16* Asrc = (tid & 1) ? Alo : Ahi;
    const __nv_bfloat16* Bsrc = (tid & 1) ? Blo : Bhi;

    uint32_t aBase = (uint32_t)(wm * 64 + (L & 15)) * 128 + ((L >> 4) << 4);
    uint32_t bBase = (uint32_t)(wn * 32 + (L & 7) + ((L >> 4) & 1) * 8) * 128
                   + (((L >> 3) & 1) << 4);

    auto loadChunk = [&](int c) {
        int k0 = c << 5;
        uint32_t sa = sbase + (uint32_t)(c % 3) * 32768;
        uint32_t sb = sa + 16384;
        const __nv_bfloat16* ap = Asrc + (size_t)(bm + ldrow) * HID + k0;
        const __nv_bfloat16* bp = Bsrc + (size_t)(bn + ldrow) * HID + k0;
#pragma unroll
        for (int i = 0; i < 4; i++) {
            uint32_t sw = SWZ((uint32_t)(ldrow * 128) + ((ldcu + i) << 4));
            cp_async16(sa + sw, ap + i * 8);
            cp_async16(sb + sw, bp + i * 8);
        }
    };

    loadChunk(0);
    asm volatile("cp.async.commit_group;" ::: "memory");
    loadChunk(1);
    asm volatile("cp.async.commit_group;" ::: "memory");

    for (int it = 0; it < 32; it++) {
        if (it + 1 < 32)
            asm volatile("cp.async.wait_group 1;" ::: "memory");
        else
            asm volatile("cp.async.wait_group 0;" ::: "memory");
        __syncthreads();
        if (it + 2 < 32) {
            loadChunk(it + 2);
            asm volatile("cp.async.commit_group;" ::: "memory");
        }

        uint32_t sa = sbase + (uint32_t)(it % 3) * 32768;
        uint32_t sb = sa + 16384;

#pragma unroll
        for (int ks = 0; ks < 2; ks++) {
            uint32_t bh[2][4], bl[2][4];
#pragma unroll
            for (int p = 0; p < 2; p++) {
                uint32_t off = bBase + (uint32_t)(p * 16 * 128) + (uint32_t)(ks * 32);
                ldmatrix_x4(bh[p], sb + SWZ(off));
                ldmatrix_x4(bl[p], sb + SWZ(off + 64));
            }
#pragma unroll
            for (int mt = 0; mt < 4; mt++) {
                uint32_t offa = aBase + (uint32_t)(mt * 16 * 128) + (uint32_t)(ks * 32);
                uint32_t ah[4], al[4];
                ldmatrix_x4(ah, sa + SWZ(offa));
#pragma unroll
                for (int nt = 0; nt < 4; nt++)
                    mma16816(acc[mt][nt], ah,
                             bh[nt >> 1][(nt & 1) * 2], bh[nt >> 1][(nt & 1) * 2 + 1]);
#pragma unroll
                for (int nt = 0; nt < 4; nt++)
                    mma16816(acc[mt][nt], ah,
                             bl[nt >> 1][(nt & 1) * 2], bl[nt >> 1][(nt & 1) * 2 + 1]);
                ldmatrix_x4(al, sa + SWZ(offa + 64));
#pragma unroll
                for (int nt = 0; nt < 4; nt++)
                    mma16816(acc[mt][nt], al,
                             bh[nt >> 1][(nt & 1) * 2], bh[nt >> 1][(nt & 1) * 2 + 1]);
            }
        }
    }
}

// ---------------------------------------------------------------------------
// Fused QKV projection: blockIdx.z in {0,1,2} selects weight/bias/dest.
// ---------------------------------------------------------------------------
__global__ void __launch_bounds__(256, 2) gemm_qkv(
    const __nv_bfloat16* __restrict__ Ahi, const __nv_bfloat16* __restrict__ Alo,
    const __nv_bfloat16* __restrict__ WhiB, const __nv_bfloat16* __restrict__ WloB,
    const float* __restrict__ bq, const float* __restrict__ bk,
    const float* __restrict__ bv,
    __nv_bfloat16* __restrict__ qhi, __nv_bfloat16* __restrict__ qlo,
    __nv_bfloat16* __restrict__ khi, __nv_bfloat16* __restrict__ klo,
    __nv_bfloat16* __restrict__ vhi, __nv_bfloat16* __restrict__ vlo)
{
    extern __shared__ __align__(1024) char smem[];
    const int z = blockIdx.z;
    const __nv_bfloat16* Bhi = WhiB + (size_t)z * HID * HID;
    const __nv_bfloat16* Blo = WloB + (size_t)z * HID * HID;
    const float* bias = (z == 0) ? bq : (z == 1) ? bk : bv;
    __nv_bfloat16* Chi = (z == 0) ? qhi : (z == 1) ? khi : vhi;
    __nv_bfloat16* Clo = (z == 0) ? qlo : (z == 1) ? klo : vlo;
    const float scale = (z == 0) ? SCALE : 1.0f;

    const int bm = blockIdx.y * 128, bn = blockIdx.x * 128;

    float acc[4][4][4];
#pragma unroll
    for (int i = 0; i < 4; i++)
#pragma unroll
        for (int j = 0; j < 4; j++)
#pragma unroll
            for (int k = 0; k < 4; k++) acc[i][j][k] = 0.f;

    gemm_core(Ahi, Alo, Bhi, Blo, bm, bn, smem_u32(smem), acc);

    const int tid = threadIdx.x, L = tid & 31, wid = tid >> 5;
    const int wm = wid >> 2, wn = wid & 3;
    const int r = L >> 2, c2 = (L & 3) * 2;
#pragma unroll
    for (int mt = 0; mt < 4; mt++) {
        int gm0 = bm + wm * 64 + mt * 16 + r;
#pragma unroll
        for (int nt = 0; nt < 4; nt++) {
            int gn = bn + wn * 32 + nt * 8 + c2;
            float b0 = bias[gn], b1 = bias[gn + 1];
            float v00 = (acc[mt][nt][0] + b0) * scale;
            float v01 = (acc[mt][nt][1] + b1) * scale;
            float v10 = (acc[mt][nt][2] + b0) * scale;
            float v11 = (acc[mt][nt][3] + b1) * scale;
            int hh = gn >> 6, d = gn & 63;
#pragma unroll
            for (int half = 0; half < 2; half++) {
                int gm = gm0 + half * 8;
                float x = half ? v10 : v00, y = half ? v11 : v01;
                int bb = gm >> 10, s = gm & 1023;
                size_t idx = ((size_t)((bb * NHEAD + hh) * SEQ) + s) * HDIM + d;
                __nv_bfloat162 hp = __floats2bfloat162_rn(x, y);
                float2 hf = __bfloat1622float2(hp);
                __nv_bfloat162 lp = __floats2bfloat162_rn(x - hf.x, y - hf.y);
                *(__nv_bfloat162*)(Chi + idx) = hp;
                *(__nv_bfloat162*)(Clo + idx) = lp;
            }
        }
    }
}

// ---------------------------------------------------------------------------
// Output projection: fp32 row-major destination.
// ---------------------------------------------------------------------------
__global__ void __launch_bounds__(256, 2) gemm_out(
    const __nv_bfloat16* __restrict__ Ahi, const __nv_bfloat16* __restrict__ Alo,
    const __nv_bfloat16* __restrict__ Bhi, const __nv_bfloat16* __restrict__ Blo,
    const float* __restrict__ bias, float* __restrict__ C)
{
    extern __shared__ __align__(1024) char smem[];
    const int bm = blockIdx.y * 128, bn = blockIdx.x * 128;

    float acc[4][4][4];
#pragma unroll
    for (int i = 0; i < 4; i++)
#pragma unroll
        for (int j = 0; j < 4; j++)
#pragma unroll
            for (int k = 0; k < 4; k++) acc[i][j][k] = 0.f;

    gemm_core(Ahi, Alo, Bhi, Blo, bm, bn, smem_u32(smem), acc);

    const int tid = threadIdx.x, L = tid & 31, wid = tid >> 5;
    const int wm = wid >> 2, wn = wid & 3;
    const int r = L >> 2, c2 = (L & 3) * 2;
#pragma unroll
    for (int mt = 0; mt < 4; mt++) {
        int gm0 = bm + wm * 64 + mt * 16 + r;
#pragma unroll
        for (int nt = 0; nt < 4; nt++) {
            int gn = bn + wn * 32 + nt * 8 + c2;
            float b0 = bias[gn], b1 = bias[gn + 1];
            float2 w0, w1;
            w0.x = acc[mt][nt][0] + b0; w0.y = acc[mt][nt][1] + b1;
            w1.x = acc[mt][nt][2] + b0; w1.y = acc[mt][nt][3] + b1;
            *(float2*)(C + (size_t)gm0 * HID + gn) = w0;
            *(float2*)(C + (size_t)(gm0 + 8) * HID + gn) = w1;
        }
    }
}

// ---------------------------------------------------------------------------
// Tensor-core flash attention, bf16-split, double-buffered KV tiles.
// CTA = 128 q-rows x one (b,h); 8 warps; KV tile = 64. 64KB dynamic smem.
// ---------------------------------------------------------------------------
__global__ void __launch_bounds__(256) attn_mma(
    const __nv_bfloat16* __restrict__ Qhi, const __nv_bfloat16* __restrict__ Qlo,
    const __nv_bfloat16* __restrict__ Khi, const __nv_bfloat16* __restrict__ Klo,
    const __nv_bfloat16* __restrict__ Vhi, const __nv_bfloat16* __restrict__ Vlo,
    __nv_bfloat16* __restrict__ Chi, __nv_bfloat16* __restrict__ Clo)
{
    extern __shared__ __align__(1024) char smem[];   // 64 KB: buf0/buf1 32KB each
    __shared__ float sCB[2][64];

    const int tid = threadIdx.x, L = tid & 31, wid = tid >> 5;
    const int b = blockIdx.z, h = blockIdx.y;
    const int qcta = blockIdx.x * 128;
    const int q0w = qcta + wid * 16;
    const uint32_t sb = smem_u32(smem);
    const size_t headbase = ((size_t)(b * NHEAD + h)) * SEQ;

    // ---- stage Q tile (128x64 hi+lo) through buf0 into A-fragments ----
    {
        const __nv_bfloat16* qh = Qhi + (headbase + qcta) * HDIM;
        const __nv_bfloat16* ql = Qlo + (headbase + qcta) * HDIM;
#pragma unroll
        for (int i = 0; i < 4; i++) {
            int u = tid + i * 256;
            int row = u >> 3, cu = u & 7;
            uint32_t sw = SWZ((uint32_t)(row * 128 + cu * 16));
            cp_async16(sb + sw, qh + (size_t)row * HDIM + cu * 8);
            cp_async16(sb + 16384 + sw, ql + (size_t)row * HDIM + cu * 8);
        }
        asm volatile("cp.async.commit_group;" ::: "memory");
        asm volatile("cp.async.wait_group 0;" ::: "memory");
        __syncthreads();
    }
    uint32_t qh[4][4], ql[4][4];
    {
        uint32_t base = (uint32_t)((wid * 16 + (L & 15)) * 128 + ((L >> 4) << 4));
#pragma unroll
        for (int ks = 0; ks < 4; ks++) {
            uint32_t off = SWZ(base + ks * 32);
            ldmatrix_x4(qh[ks], sb + off);
            ldmatrix_x4(ql[ks], sb + 16384 + off);
        }
    }
    __syncthreads();   // Q fully consumed; buffers free for KV

    const int nr0 = g_nearest[b * SEQ + q0w + (L >> 2)];
    const int nr1 = g_nearest[b * SEQ + q0w + (L >> 2) + 8];

    float o[8][4];
#pragma unroll
    for (int i = 0; i < 8; i++)
#pragma unroll
        for (int j = 0; j < 4; j++) o[i][j] = 0.f;
    float m0 = -1e30f, m1 = -1e30f, l0 = 0.f, l1 = 0.f;

    uint32_t kBase = (uint32_t)((L & 7) + ((L >> 4) & 1) * 8) * 128
                   + (((L >> 3) & 1) << 4);
    uint32_t vBase = (uint32_t)((L & 7) + ((L >> 3) & 1) * 8) * 128
                   + ((L >> 4) << 4);

    auto issueTile = [&](int t) {
        int buf = t & 1;
        uint32_t base = sb + buf * 32768;
        int kt = t * 64;
        const __nv_bfloat16* kh = Khi + (headbase + kt) * HDIM;
        const __nv_bfloat16* kl = Klo + (headbase + kt) * HDIM;
        const __nv_bfloat16* vh = Vhi + (headbase + kt) * HDIM;
        const __nv_bfloat16* vl = Vlo + (headbase + kt) * HDIM;
#pragma unroll
        for (int i = 0; i < 2; i++) {
            int u = tid + i * 256;
            int row = u >> 3, cu = u & 7;
            uint32_t sw = SWZ((uint32_t)(row * 128 + cu * 16));
            size_t g = (size_t)row * HDIM + cu * 8;
            cp_async16(base + sw,         kh + g);
            cp_async16(base +  8192 + sw, kl + g);
            cp_async16(base + 16384 + sw, vh + g);
            cp_async16(base + 24576 + sw, vl + g);
        }
        if (tid < 64) sCB[buf][tid] = g_colbias[b * SEQ + kt + tid];
        asm volatile("cp.async.commit_group;" ::: "memory");
    };

    issueTile(0);
    issueTile(1);

    for (int it = 0; it < 16; it++) {
        if (it + 1 < 16)
            asm volatile("cp.async.wait_group 1;" ::: "memory");
        else
            asm volatile("cp.async.wait_group 0;" ::: "memory");
        __syncthreads();

        const int buf = it & 1;
        const uint32_t base = sb + buf * 32768;
        const int kt = it * 64;

        // ---- S = Qh*Kh + Qh*Kl + Ql*Kh ----
        float s[8][4];
#pragma unroll
        for (int i = 0; i < 8; i++)
#pragma unroll
            for (int j = 0; j < 4; j++) s[i][j] = 0.f;

#pragma unroll
        for (int ks = 0; ks < 4; ks++) {
#pragma unroll
            for (int p = 0; p < 4; p++) {
                uint32_t off = SWZ(kBase + (uint32_t)(p * 16 * 128) + (uint32_t)(ks * 32));
                uint32_t f[4];
                ldmatrix_x4(f, base + off);                 // K hi
                mma16816(s[2*p],   qh[ks], f[0], f[1]);
                mma16816(s[2*p],   ql[ks], f[0], f[1]);
                mma16816(s[2*p+1], qh[ks], f[2], f[3]);
                mma16816(s[2*p+1], ql[ks], f[2], f[3]);
                ldmatrix_x4(f, base + 8192 + off);          // K lo
                mma16816(s[2*p],   qh[ks], f[0], f[1]);
                mma16816(s[2*p+1], qh[ks], f[2], f[3]);
            }
        }

        // ---- bias + online softmax ----
        int colb = kt + 2 * (L & 3);
        float t0 = -1e30f, t1 = -1e30f;
#pragma unroll
        for (int nb = 0; nb < 8; nb++) {
            float c0 = sCB[buf][nb * 8 + 2 * (L & 3)];
            float c1 = sCB[buf][nb * 8 + 2 * (L & 3) + 1];
            int g0 = colb + nb * 8, g1 = g0 + 1;
            s[nb][0] += c0 + (g0 == nr0 ? 2.f : 0.f);
            s[nb][1] += c1 + (g1 == nr0 ? 2.f : 0.f);
            s[nb][2] += c0 + (g0 == nr1 ? 2.f : 0.f);
            s[nb][3] += c1 + (g1 == nr1 ? 2.f : 0.f);
            t0 = fmaxf(t0, fmaxf(s[nb][0], s[nb][1]));
            t1 = fmaxf(t1, fmaxf(s[nb][2], s[nb][3]));
        }
        t0 = fmaxf(t0, __shfl_xor_sync(0xffffffffu, t0, 1));
        t0 = fmaxf(t0, __shfl_xor_sync(0xffffffffu, t0, 2));
        t1 = fmaxf(t1, __shfl_xor_sync(0xffffffffu, t1, 1));
        t1 = fmaxf(t1, __shfl_xor_sync(0xffffffffu, t1, 2));
        float nm0 = fmaxf(m0, t0), nm1 = fmaxf(m1, t1);
        float cr0 = __expf(m0 - nm0), cr1 = __expf(m1 - nm1);
        m0 = nm0; m1 = nm1;
        l0 *= cr0; l1 *= cr1;
#pragma unroll
        for (int nb = 0; nb < 8; nb++) {
            o[nb][0] *= cr0; o[nb][1] *= cr0;
            o[nb][2] *= cr1; o[nb][3] *= cr1;
            s[nb][0] = __expf(s[nb][0] - m0); l0 += s[nb][0];
            s[nb][1] = __expf(s[nb][1] - m0); l0 += s[nb][1];
            s[nb][2] = __expf(s[nb][2] - m1); l1 += s[nb][2];
            s[nb][3] = __expf(s[nb][3] - m1); l1 += s[nb][3];
        }

        // ---- O += Ph*Vh + Ph*Vl + Pl*Vh ----
#pragma unroll
        for (int ks = 0; ks < 4; ks++) {
            uint32_t ah[4], al[4];
#pragma unroll
            for (int half = 0; half < 2; half++) {
                int nb = 2 * ks + half;
                __nv_bfloat162 h01 = __floats2bfloat162_rn(s[nb][0], s[nb][1]);
                __nv_bfloat162 h23 = __floats2bfloat162_rn(s[nb][2], s[nb][3]);
                float2 f01 = __bfloat1622float2(h01);
                float2 f23 = __bfloat1622float2(h23);
                ah[2*half]   = *(uint32_t*)&h01;
                ah[2*half+1] = *(uint32_t*)&h23;
                al[2*half]   = pack_bf2(s[nb][0] - f01.x, s[nb][1] - f01.y);
                al[2*half+1] = pack_bf2(s[nb][2] - f23.x, s[nb][3] - f23.y);
            }
#pragma unroll
            for (int p = 0; p < 4; p++) {
                uint32_t off = SWZ(vBase + (uint32_t)(ks * 16 * 128) + (uint32_t)(p * 32));
                uint32_t f[4];
                ldmatrix_x4_t(f, base + 16384 + off);       // V hi
                mma16816(o[2*p],   ah, f[0], f[1]);
                mma16816(o[2*p],   al, f[0], f[1]);
                mma16816(o[2*p+1], ah, f[2], f[3]);
                mma16816(o[2*p+1], al, f[2], f[3]);
                ldmatrix_x4_t(f, base + 24576 + off);       // V lo
                mma16816(o[2*p],   ah, f[0], f[1]);
                mma16816(o[2*p+1], ah, f[2], f[3]);
            }
        }

        __syncthreads();                 // all warps done with buf
        if (it + 2 < 16) issueTile(it + 2);
    }

    // ---- finalize ----
    l0 += __shfl_xor_sync(0xffffffffu, l0, 1);
    l0 += __shfl_xor_sync(0xffffffffu, l0, 2);
    l1 += __shfl_xor_sync(0xffffffffu, l1, 1);
    l1 += __shfl_xor_sync(0xffffffffu, l1, 2);
    float inv0 = 1.f / l0, inv1 = 1.f / l1;

    int r0g = q0w + (L >> 2), r1g = r0g + 8;
    size_t base0 = (size_t)(b * SEQ + r0g) * HID + h * HDIM + 2 * (L & 3);
    size_t base1 = (size_t)(b * SEQ + r1g) * HID + h * HDIM + 2 * (L & 3);
#pragma unroll
    for (int nb = 0; nb < 8; nb++) {
        float x0 = o[nb][0] * inv0, y0 = o[nb][1] * inv0;
        float x1 = o[nb][2] * inv1, y1 = o[nb][3] * inv1;
        __nv_bfloat162 hp0 = __floats2bfloat162_rn(x0, y0);
        __nv_bfloat162 hp1 = __floats2bfloat162_rn(x1, y1);
        float2 hf0 = __bfloat1622float2(hp0);
        float2 hf1 = __bfloat1622float2(hp1);
        __nv_bfloat162 lp0 = __floats2bfloat162_rn(x0 - hf0.x, y0 - hf0.y);
        __nv_bfloat162 lp1 = __floats2bfloat162_rn(x1 - hf1.x, y1 - hf1.y);
        *(__nv_bfloat162*)(Chi + base0 + nb * 8) = hp0;
        *(__nv_bfloat162*)(Clo + base0 + nb * 8) = lp0;
        *(__nv_bfloat162*)(Chi + base1 + nb * 8) = hp1;
        *(__nv_bfloat162*)(Clo + base1 + nb * 8) = lp1;
    }
}

// ---------------------------------------------------------------------------
extern "C" void kernel_launch(void* const* d_in, const int* in_sizes, int n_in,
                              void* d_out, int out_size)
{
    const float* hs     = (const float*)d_in[0];
    const int*   morpho = (const int*)  d_in[1];
    const float* Wq = (const float*)d_in[2];
    const float* bq = (const float*)d_in[3];
    const float* Wk = (const float*)d_in[4];
    const float* bk = (const float*)d_in[5];
    const float* Wv = (const float*)d_in[6];
    const float* bv = (const float*)d_in[7];
    const float* Wo = (const float*)d_in[8];
    const float* bo = (const float*)d_in[9];
    float* out = (float*)d_out;

    __nv_bfloat16 *ahi, *alo, *whi, *wlo;
    __nv_bfloat16 *qhi, *qlo, *khi, *klo, *vhi, *vlo;
    cudaGetSymbolAddress((void**)&ahi, g_Ahi);
    cudaGetSymbolAddress((void**)&alo, g_Alo);
    cudaGetSymbolAddress((void**)&whi, g_Whi);
    cudaGetSymbolAddress((void**)&wlo, g_Wlo);
    cudaGetSymbolAddress((void**)&qhi, g_Qhi);
    cudaGetSymbolAddress((void**)&qlo, g_Qlo);
    cudaGetSymbolAddress((void**)&khi, g_Khi);
    cudaGetSymbolAddress((void**)&klo, g_Klo);
    cudaGetSymbolAddress((void**)&vhi, g_Vhi);
    cudaGetSymbolAddress((void**)&vlo, g_Vlo);

    static bool attr_set = false;
    if (!attr_set) {
        cudaFuncSetAttribute(gemm_qkv,
                             cudaFuncAttributeMaxDynamicSharedMemorySize, 98304);
        cudaFuncSetAttribute(gemm_out,
                             cudaFuncAttributeMaxDynamicSharedMemorySize, 98304);
        cudaFuncSetAttribute(attn_mma,
                             cudaFuncAttributeMaxDynamicSharedMemorySize, 65536);
        attr_set = true;
    }

    bias_kernel<<<dim3(BATCH, SEQ/128), 128>>>(morpho);

    split_kernel<<<MTOT*HID/1024, 256>>>((const float4*)hs,
                                         (__nv_bfloat162*)ahi, (__nv_bfloat162*)alo);

    wtrans_kernel<<<dim3(HID/32, HID/32, 4), dim3(32, 8)>>>(
        Wq, Wk, Wv, Wo, whi, wlo);

    gemm_qkv<<<dim3(HID/128, MTOT/128, 3), 256, 98304>>>(
        ahi, alo, whi, wlo, bq, bk, bv, qhi, qlo, khi, klo, vhi, vlo);

    attn_mma<<<dim3(SEQ/128, NHEAD, BATCH), 256, 65536>>>(
        qhi, qlo, khi, klo, vhi, vlo, ahi, alo);

    gemm_out<<<dim3(HID/128, MTOT/128), 256, 98304>>>(
        ahi, alo, whi + 3*(size_t)HID*HID, wlo + 3*(size_t)HID*HID, bo, out);
}

// round 12
// speedup vs baseline: 1.1038x; 1.1038x over previous
#include <cuda_runtime.h>
#include <cuda_bf16.h>
#include <cstdint>
#include <math.h>

#define BATCH 4
#define SEQ   1024
#define HID   1024
#define NHEAD 16
#define HDIM  64
#define SCALE 0.125f
#define MTOT  (BATCH*SEQ)

// ------------------------- scratch (device globals) -------------------------
__device__ __nv_bfloat16 g_Ahi[MTOT*HID];        // hi/lo split of GEMM A input
__device__ __nv_bfloat16 g_Alo[MTOT*HID];
__device__ __nv_bfloat16 g_Whi[4*HID*HID];       // transposed weights [N][K], 4 slots
__device__ __nv_bfloat16 g_Wlo[4*HID*HID];
// Q/K/V bf16 hi/lo, head-major [b][h][s][d]
__device__ __nv_bfloat16 g_Qhi[MTOT*HID];
__device__ __nv_bfloat16 g_Qlo[MTOT*HID];
__device__ __nv_bfloat16 g_Khi[MTOT*HID];
__device__ __nv_bfloat16 g_Klo[MTOT*HID];
__device__ __nv_bfloat16 g_Vhi[MTOT*HID];
__device__ __nv_bfloat16 g_Vlo[MTOT*HID];
__device__ int   g_nearest[BATCH*SEQ];
__device__ float g_colbias[BATCH*SEQ];

// ------------------------------ PTX helpers ---------------------------------
__device__ __forceinline__ uint32_t smem_u32(const void* p) {
    uint32_t a;
    asm("{ .reg .u64 t; cvta.to.shared.u64 t, %1; cvt.u32.u64 %0, t; }"
        : "=r"(a) : "l"(p));
    return a;
}

__device__ __forceinline__ void cp_async16(uint32_t saddr, const void* gaddr) {
    asm volatile("cp.async.cg.shared.global [%0], [%1], 16;"
                 :: "r"(saddr), "l"(gaddr) : "memory");
}

__device__ __forceinline__ void ldmatrix_x4(uint32_t* r, uint32_t addr) {
    asm volatile("ldmatrix.sync.aligned.m8n8.x4.shared.b16 {%0,%1,%2,%3}, [%4];"
                 : "=r"(r[0]), "=r"(r[1]), "=r"(r[2]), "=r"(r[3]) : "r"(addr));
}

__device__ __forceinline__ void ldmatrix_x4_t(uint32_t* r, uint32_t addr) {
    asm volatile("ldmatrix.sync.aligned.m8n8.x4.trans.shared.b16 {%0,%1,%2,%3}, [%4];"
                 : "=r"(r[0]), "=r"(r[1]), "=r"(r[2]), "=r"(r[3]) : "r"(addr));
}

__device__ __forceinline__ void mma16816(float* d, const uint32_t* a,
                                         uint32_t b0, uint32_t b1) {
    asm volatile(
        "mma.sync.aligned.m16n8k16.row.col.f32.bf16.bf16.f32 "
        "{%0,%1,%2,%3}, {%4,%5,%6,%7}, {%8,%9}, {%0,%1,%2,%3};"
        : "+f"(d[0]), "+f"(d[1]), "+f"(d[2]), "+f"(d[3])
        : "r"(a[0]), "r"(a[1]), "r"(a[2]), "r"(a[3]), "r"(b0), "r"(b1));
}

#define SWZ(x) ((x) ^ (((x) >> 3) & 0x70))

__device__ __forceinline__ uint32_t pack_bf2(float x, float y) {
    __nv_bfloat162 h = __floats2bfloat162_rn(x, y);
    return *(uint32_t*)&h;
}

// ---------------------------------------------------------------------------
// Morphological bias precompute (parallelized: 32 blocks)
// ---------------------------------------------------------------------------
__global__ void bias_kernel(const int* __restrict__ morpho)
{
    int b = blockIdx.x;
    __shared__ int types[SEQ];
    for (int i = threadIdx.x; i < SEQ; i += blockDim.x)
        types[i] = morpho[b*SEQ + i];
    __syncthreads();
    int q = blockIdx.y * 128 + threadIdx.x;
    int best = -1;
    int bestd = 1 << 30;
    for (int j = 0; j < SEQ; j++) {
        if (types[j] == 2) {
            int d = abs(q - j);
            if (d < bestd) { bestd = d; best = j; }
        }
    }
    g_nearest[b*SEQ + q] = best;
    int t = types[q];
    float cb = 0.0f;
    if (t == 0) cb = 0.75f;
    else if (t == 1) cb = 0.36f;
    g_colbias[b*SEQ + q] = cb;
}

// ---------------------------------------------------------------------------
// fp32 -> bf16 hi/lo split (row-major, vectorized by 4)
// ---------------------------------------------------------------------------
__global__ void __launch_bounds__(256) split_kernel(
    const float4* __restrict__ src, __nv_bfloat162* __restrict__ hi,
    __nv_bfloat162* __restrict__ lo)
{
    int i = blockIdx.x * 256 + threadIdx.x;
    float4 v = src[i];
    __nv_bfloat16 h0 = __float2bfloat16(v.x);
    __nv_bfloat16 h1 = __float2bfloat16(v.y);
    __nv_bfloat16 h2 = __float2bfloat16(v.z);
    __nv_bfloat16 h3 = __float2bfloat16(v.w);
    __nv_bfloat162 ha; ha.x = h0; ha.y = h1;
    __nv_bfloat162 hb; hb.x = h2; hb.y = h3;
    hi[2*i] = ha; hi[2*i+1] = hb;
    __nv_bfloat162 la, lb;
    la.x = __float2bfloat16(v.x - __bfloat162float(h0));
    la.y = __float2bfloat16(v.y - __bfloat162float(h1));
    lb.x = __float2bfloat16(v.z - __bfloat162float(h2));
    lb.y = __float2bfloat16(v.w - __bfloat162float(h3));
    lo[2*i] = la; lo[2*i+1] = lb;
}

// ---------------------------------------------------------------------------
// W [K][N] fp32 -> Wt hi/lo [N][K] bf16 (transpose + split), z = weight slot
// ---------------------------------------------------------------------------
__global__ void wtrans_kernel(const float* __restrict__ W0,
                              const float* __restrict__ W1,
                              const float* __restrict__ W2,
                              const float* __restrict__ W3,
                              __nv_bfloat16* __restrict__ hiB,
                              __nv_bfloat16* __restrict__ loB)
{
    int z = blockIdx.z;
    const float* W = (z == 0) ? W0 : (z == 1) ? W1 : (z == 2) ? W2 : W3;
    __nv_bfloat16* hi = hiB + (size_t)z * HID * HID;
    __nv_bfloat16* lo = loB + (size_t)z * HID * HID;

    __shared__ float t[32][33];
    int n0 = blockIdx.x * 32, k0 = blockIdx.y * 32;
    int c = threadIdx.x, r0 = threadIdx.y;        // 32 x 8
#pragma unroll
    for (int i = 0; i < 4; i++)
        t[r0 + 8*i][c] = W[(size_t)(k0 + r0 + 8*i) * HID + n0 + c];
    __syncthreads();
#pragma unroll
    for (int i = 0; i < 4; i++) {
        int rr = r0 + 8*i;
        float v = t[c][rr];
        __nv_bfloat16 h = __float2bfloat16(v);
        hi[(size_t)(n0 + rr) * HID + k0 + c] = h;
        lo[(size_t)(n0 + rr) * HID + k0 + c] =
            __float2bfloat16(v - __bfloat162float(h));
    }
}

// ---------------------------------------------------------------------------
// GEMM mainloop (R9 structure: 3 sequential K-passes, RAW distance 16) with
// 3-stage pipeline: A bufs [0,48K), B bufs [48K,96K), prefetch depth 2,
// wait_group 1. K chunk = 64.
// ---------------------------------------------------------------------------
__device__ __forceinline__ void gemm_core(
    const __nv_bfloat16* __restrict__ Ahi, const __nv_bfloat16* __restrict__ Alo,
    const __nv_bfloat16* __restrict__ Bhi, const __nv_bfloat16* __restrict__ Blo,
    int bm, int bn, uint32_t sbase, float acc[4][4][4])
{
    const int tid = threadIdx.x;
    const int L = tid & 31;
    const int wid = tid >> 5;
    const int wm = wid >> 2;
    const int wn = wid & 3;

    const int ldrow = tid >> 1;
    const int ldcu  = (tid & 1) * 4;

    uint32_t aRow = (uint32_t)(wm * 64 + (L & 15)) * 128 + ((L >> 4) << 4);
    uint32_t bRow = (uint32_t)(wn * 32 + (L & 7) + ((L >> 4) & 1) * 8) * 128
                  + (((L >> 3) & 1) << 4);

    auto loadChunk = [&](int it) {
        int pass = it >> 4;
        int k0 = (it & 15) << 6;
        int buf = it % 3;
        const __nv_bfloat16* Ap = (pass == 2) ? Alo : Ahi;
        const __nv_bfloat16* Bp = (pass == 1) ? Blo : Bhi;
        uint32_t sa = sbase + (uint32_t)buf * 16384;
        uint32_t sb = sbase + 49152 + (uint32_t)buf * 16384;
#pragma unroll
        for (int i = 0; i < 4; i++) {
            uint32_t off = (uint32_t)(ldrow * 128) + ((ldcu + i) << 4);
            uint32_t sw = SWZ(off);
            cp_async16(sa + sw, Ap + (size_t)(bm + ldrow) * HID + k0 + ((ldcu + i) << 3));
            cp_async16(sb + sw, Bp + (size_t)(bn + ldrow) * HID + k0 + ((ldcu + i) << 3));
        }
    };

    loadChunk(0);
    asm volatile("cp.async.commit_group;" ::: "memory");
    loadChunk(1);
    asm volatile("cp.async.commit_group;" ::: "memory");

    for (int it = 0; it < 48; it++) {
        if (it + 1 < 48)
            asm volatile("cp.async.wait_group 1;" ::: "memory");
        else
            asm volatile("cp.async.wait_group 0;" ::: "memory");
        __syncthreads();
        if (it + 2 < 48) {
            loadChunk(it + 2);
            asm volatile("cp.async.commit_group;" ::: "memory");
        }

        int buf = it % 3;
        uint32_t sa = sbase + (uint32_t)buf * 16384;
        uint32_t sb = sbase + 49152 + (uint32_t)buf * 16384;

#pragma unroll
        for (int ks = 0; ks < 4; ks++) {
            uint32_t a[4][4], b[2][4];
#pragma unroll
            for (int mt = 0; mt < 4; mt++) {
                uint32_t off = aRow + (uint32_t)(mt * 16 * 128) + (uint32_t)(ks * 32);
                ldmatrix_x4(a[mt], sa + SWZ(off));
            }
#pragma unroll
            for (int p = 0; p < 2; p++) {
                uint32_t off = bRow + (uint32_t)(p * 16 * 128) + (uint32_t)(ks * 32);
                ldmatrix_x4(b[p], sb + SWZ(off));
            }
#pragma unroll
            for (int mt = 0; mt < 4; mt++)
#pragma unroll
                for (int nt = 0; nt < 4; nt++)
                    mma16816(acc[mt][nt], a[mt],
                             b[nt >> 1][(nt & 1) * 2], b[nt >> 1][(nt & 1) * 2 + 1]);
        }
    }
}

// ---------------------------------------------------------------------------
// Fused QKV projection: blockIdx.z in {0,1,2} selects weight/bias/dest.
// ---------------------------------------------------------------------------
__global__ void __launch_bounds__(256, 2) gemm_qkv(
    const __nv_bfloat16* __restrict__ Ahi, const __nv_bfloat16* __restrict__ Alo,
    const __nv_bfloat16* __restrict__ WhiB, const __nv_bfloat16* __restrict__ WloB,
    const float* __restrict__ bq, const float* __restrict__ bk,
    const float* __restrict__ bv,
    __nv_bfloat16* __restrict__ qhi, __nv_bfloat16* __restrict__ qlo,
    __nv_bfloat16* __restrict__ khi, __nv_bfloat16* __restrict__ klo,
    __nv_bfloat16* __restrict__ vhi, __nv_bfloat16* __restrict__ vlo)
{
    extern __shared__ __align__(1024) char smem[];
    const int z = blockIdx.z;
    const __nv_bfloat16* Bhi = WhiB + (size_t)z * HID * HID;
    const __nv_bfloat16* Blo = WloB + (size_t)z * HID * HID;
    const float* bias = (z == 0) ? bq : (z == 1) ? bk : bv;
    __nv_bfloat16* Chi = (z == 0) ? qhi : (z == 1) ? khi : vhi;
    __nv_bfloat16* Clo = (z == 0) ? qlo : (z == 1) ? klo : vlo;
    const float scale = (z == 0) ? SCALE : 1.0f;

    const int bm = blockIdx.y * 128, bn = blockIdx.x * 128;

    float acc[4][4][4];
#pragma unroll
    for (int i = 0; i < 4; i++)
#pragma unroll
        for (int j = 0; j < 4; j++)
#pragma unroll
            for (int k = 0; k < 4; k++) acc[i][j][k] = 0.f;

    gemm_core(Ahi, Alo, Bhi, Blo, bm, bn, smem_u32(smem), acc);

    const int tid = threadIdx.x, L = tid & 31, wid = tid >> 5;
    const int wm = wid >> 2, wn = wid & 3;
    const int r = L >> 2, c2 = (L & 3) * 2;
#pragma unroll
    for (int mt = 0; mt < 4; mt++) {
        int gm0 = bm + wm * 64 + mt * 16 + r;
#pragma unroll
        for (int nt = 0; nt < 4; nt++) {
            int gn = bn + wn * 32 + nt * 8 + c2;
            float b0 = bias[gn], b1 = bias[gn + 1];
            float v00 = (acc[mt][nt][0] + b0) * scale;
            float v01 = (acc[mt][nt][1] + b1) * scale;
            float v10 = (acc[mt][nt][2] + b0) * scale;
            float v11 = (acc[mt][nt][3] + b1) * scale;
            int hh = gn >> 6, d = gn & 63;
#pragma unroll
            for (int half = 0; half < 2; half++) {
                int gm = gm0 + half * 8;
                float x = half ? v10 : v00, y = half ? v11 : v01;
                int bb = gm >> 10, s = gm & 1023;
                size_t idx = ((size_t)((bb * NHEAD + hh) * SEQ) + s) * HDIM + d;
                __nv_bfloat162 hp = __floats2bfloat162_rn(x, y);
                float2 hf = __bfloat1622float2(hp);
                __nv_bfloat162 lp = __floats2bfloat162_rn(x - hf.x, y - hf.y);
                *(__nv_bfloat162*)(Chi + idx) = hp;
                *(__nv_bfloat162*)(Clo + idx) = lp;
            }
        }
    }
}

// ---------------------------------------------------------------------------
// Output projection: fp32 row-major destination.
// ---------------------------------------------------------------------------
__global__ void __launch_bounds__(256, 2) gemm_out(
    const __nv_bfloat16* __restrict__ Ahi, const __nv_bfloat16* __restrict__ Alo,
    const __nv_bfloat16* __restrict__ Bhi, const __nv_bfloat16* __restrict__ Blo,
    const float* __restrict__ bias, float* __restrict__ C)
{
    extern __shared__ __align__(1024) char smem[];
    const int bm = blockIdx.y * 128, bn = blockIdx.x * 128;

    float acc[4][4][4];
#pragma unroll
    for (int i = 0; i < 4; i++)
#pragma unroll
        for (int j = 0; j < 4; j++)
#pragma unroll
            for (int k = 0; k < 4; k++) acc[i][j][k] = 0.f;

    gemm_core(Ahi, Alo, Bhi, Blo, bm, bn, smem_u32(smem), acc);

    const int tid = threadIdx.x, L = tid & 31, wid = tid >> 5;
    const int wm = wid >> 2, wn = wid & 3;
    const int r = L >> 2, c2 = (L & 3) * 2;
#pragma unroll
    for (int mt = 0; mt < 4; mt++) {
        int gm0 = bm + wm * 64 + mt * 16 + r;
#pragma unroll
        for (int nt = 0; nt < 4; nt++) {
            int gn = bn + wn * 32 + nt * 8 + c2;
            float b0 = bias[gn], b1 = bias[gn + 1];
            float2 w0, w1;
            w0.x = acc[mt][nt][0] + b0; w0.y = acc[mt][nt][1] + b1;
            w1.x = acc[mt][nt][2] + b0; w1.y = acc[mt][nt][3] + b1;
            *(float2*)(C + (size_t)gm0 * HID + gn) = w0;
            *(float2*)(C + (size_t)(gm0 + 8) * HID + gn) = w1;
        }
    }
}

// ---------------------------------------------------------------------------
// Tensor-core flash attention, bf16-split, double-buffered KV tiles.
// CTA = 128 q-rows x one (b,h); 8 warps; KV tile = 64. 64KB dynamic smem.
// ---------------------------------------------------------------------------
__global__ void __launch_bounds__(256) attn_mma(
    const __nv_bfloat16* __restrict__ Qhi, const __nv_bfloat16* __restrict__ Qlo,
    const __nv_bfloat16* __restrict__ Khi, const __nv_bfloat16* __restrict__ Klo,
    const __nv_bfloat16* __restrict__ Vhi, const __nv_bfloat16* __restrict__ Vlo,
    __nv_bfloat16* __restrict__ Chi, __nv_bfloat16* __restrict__ Clo)
{
    extern __shared__ __align__(1024) char smem[];   // 64 KB: buf0/buf1 32KB each
    __shared__ float sCB[2][64];

    const int tid = threadIdx.x, L = tid & 31, wid = tid >> 5;
    const int b = blockIdx.z, h = blockIdx.y;
    const int qcta = blockIdx.x * 128;
    const int q0w = qcta + wid * 16;
    const uint32_t sb = smem_u32(smem);
    const size_t headbase = ((size_t)(b * NHEAD + h)) * SEQ;

    // ---- stage Q tile (128x64 hi+lo) through buf0 into A-fragments ----
    {
        const __nv_bfloat16* qh = Qhi + (headbase + qcta) * HDIM;
        const __nv_bfloat16* ql = Qlo + (headbase + qcta) * HDIM;
#pragma unroll
        for (int i = 0; i < 4; i++) {
            int u = tid + i * 256;
            int row = u >> 3, cu = u & 7;
            uint32_t sw = SWZ((uint32_t)(row * 128 + cu * 16));
            cp_async16(sb + sw, qh + (size_t)row * HDIM + cu * 8);
            cp_async16(sb + 16384 + sw, ql + (size_t)row * HDIM + cu * 8);
        }
        asm volatile("cp.async.commit_group;" ::: "memory");
        asm volatile("cp.async.wait_group 0;" ::: "memory");
        __syncthreads();
    }
    uint32_t qh[4][4], ql[4][4];
    {
        uint32_t base = (uint32_t)((wid * 16 + (L & 15)) * 128 + ((L >> 4) << 4));
#pragma unroll
        for (int ks = 0; ks < 4; ks++) {
            uint32_t off = SWZ(base + ks * 32);
            ldmatrix_x4(qh[ks], sb + off);
            ldmatrix_x4(ql[ks], sb + 16384 + off);
        }
    }
    __syncthreads();   // Q fully consumed; buffers free for KV

    const int nr0 = g_nearest[b * SEQ + q0w + (L >> 2)];
    const int nr1 = g_nearest[b * SEQ + q0w + (L >> 2) + 8];

    float o[8][4];
#pragma unroll
    for (int i = 0; i < 8; i++)
#pragma unroll
        for (int j = 0; j < 4; j++) o[i][j] = 0.f;
    float m0 = -1e30f, m1 = -1e30f, l0 = 0.f, l1 = 0.f;

    uint32_t kBase = (uint32_t)((L & 7) + ((L >> 4) & 1) * 8) * 128
                   + (((L >> 3) & 1) << 4);
    uint32_t vBase = (uint32_t)((L & 7) + ((L >> 3) & 1) * 8) * 128
                   + ((L >> 4) << 4);

    auto issueTile = [&](int t) {
        int buf = t & 1;
        uint32_t base = sb + buf * 32768;
        int kt = t * 64;
        const __nv_bfloat16* kh = Khi + (headbase + kt) * HDIM;
        const __nv_bfloat16* kl = Klo + (headbase + kt) * HDIM;
        const __nv_bfloat16* vh = Vhi + (headbase + kt) * HDIM;
        const __nv_bfloat16* vl = Vlo + (headbase + kt) * HDIM;
#pragma unroll
        for (int i = 0; i < 2; i++) {
            int u = tid + i * 256;
            int row = u >> 3, cu = u & 7;
            uint32_t sw = SWZ((uint32_t)(row * 128 + cu * 16));
            size_t g = (size_t)row * HDIM + cu * 8;
            cp_async16(base + sw,         kh + g);
            cp_async16(base +  8192 + sw, kl + g);
            cp_async16(base + 16384 + sw, vh + g);
            cp_async16(base + 24576 + sw, vl + g);
        }
        if (tid < 64) sCB[buf][tid] = g_colbias[b * SEQ + kt + tid];
        asm volatile("cp.async.commit_group;" ::: "memory");
    };

    issueTile(0);
    issueTile(1);

    for (int it = 0; it < 16; it++) {
        if (it + 1 < 16)
            asm volatile("cp.async.wait_group 1;" ::: "memory");
        else
            asm volatile("cp.async.wait_group 0;" ::: "memory");
        __syncthreads();

        const int buf = it & 1;
        const uint32_t base = sb + buf * 32768;
        const int kt = it * 64;

        // ---- S = Qh*Kh + Qh*Kl + Ql*Kh ----
        float s[8][4];
#pragma unroll
        for (int i = 0; i < 8; i++)
#pragma unroll
            for (int j = 0; j < 4; j++) s[i][j] = 0.f;

#pragma unroll
        for (int ks = 0; ks < 4; ks++) {
#pragma unroll
            for (int p = 0; p < 4; p++) {
                uint32_t off = SWZ(kBase + (uint32_t)(p * 16 * 128) + (uint32_t)(ks * 32));
                uint32_t f[4];
                ldmatrix_x4(f, base + off);                 // K hi
                mma16816(s[2*p],   qh[ks], f[0], f[1]);
                mma16816(s[2*p],   ql[ks], f[0], f[1]);
                mma16816(s[2*p+1], qh[ks], f[2], f[3]);
                mma16816(s[2*p+1], ql[ks], f[2], f[3]);
                ldmatrix_x4(f, base + 8192 + off);          // K lo
                mma16816(s[2*p],   qh[ks], f[0], f[1]);
                mma16816(s[2*p+1], qh[ks], f[2], f[3]);
            }
        }

        // ---- bias + online softmax ----
        int colb = kt + 2 * (L & 3);
        float t0 = -1e30f, t1 = -1e30f;
#pragma unroll
        for (int nb = 0; nb < 8; nb++) {
            float c0 = sCB[buf][nb * 8 + 2 * (L & 3)];
            float c1 = sCB[buf][nb * 8 + 2 * (L & 3) + 1];
            int g0 = colb + nb * 8, g1 = g0 + 1;
            s[nb][0] += c0 + (g0 == nr0 ? 2.f : 0.f);
            s[nb][1] += c1 + (g1 == nr0 ? 2.f : 0.f);
            s[nb][2] += c0 + (g0 == nr1 ? 2.f : 0.f);
            s[nb][3] += c1 + (g1 == nr1 ? 2.f : 0.f);
            t0 = fmaxf(t0, fmaxf(s[nb][0], s[nb][1]));
            t1 = fmaxf(t1, fmaxf(s[nb][2], s[nb][3]));
        }
        t0 = fmaxf(t0, __shfl_xor_sync(0xffffffffu, t0, 1));
        t0 = fmaxf(t0, __shfl_xor_sync(0xffffffffu, t0, 2));
        t1 = fmaxf(t1, __shfl_xor_sync(0xffffffffu, t1, 1));
        t1 = fmaxf(t1, __shfl_xor_sync(0xffffffffu, t1, 2));
        float nm0 = fmaxf(m0, t0), nm1 = fmaxf(m1, t1);
        float cr0 = __expf(m0 - nm0), cr1 = __expf(m1 - nm1);
        m0 = nm0; m1 = nm1;
        l0 *= cr0; l1 *= cr1;
#pragma unroll
        for (int nb = 0; nb < 8; nb++) {
            o[nb][0] *= cr0; o[nb][1] *= cr0;
            o[nb][2] *= cr1; o[nb][3] *= cr1;
            s[nb][0] = __expf(s[nb][0] - m0); l0 += s[nb][0];
            s[nb][1] = __expf(s[nb][1] - m0); l0 += s[nb][1];
            s[nb][2] = __expf(s[nb][2] - m1); l1 += s[nb][2];
            s[nb][3] = __expf(s[nb][3] - m1); l1 += s[nb][3];
        }

        // ---- O += Ph*Vh + Ph*Vl + Pl*Vh ----
#pragma unroll
        for (int ks = 0; ks < 4; ks++) {
            uint32_t ah[4], al[4];
#pragma unroll
            for (int half = 0; half < 2; half++) {
                int nb = 2 * ks + half;
                __nv_bfloat162 h01 = __floats2bfloat162_rn(s[nb][0], s[nb][1]);
                __nv_bfloat162 h23 = __floats2bfloat162_rn(s[nb][2], s[nb][3]);
                float2 f01 = __bfloat1622float2(h01);
                float2 f23 = __bfloat1622float2(h23);
                ah[2*half]   = *(uint32_t*)&h01;
                ah[2*half+1] = *(uint32_t*)&h23;
                al[2*half]   = pack_bf2(s[nb][0] - f01.x, s[nb][1] - f01.y);
                al[2*half+1] = pack_bf2(s[nb][2] - f23.x, s[nb][3] - f23.y);
            }
#pragma unroll
            for (int p = 0; p < 4; p++) {
                uint32_t off = SWZ(vBase + (uint32_t)(ks * 16 * 128) + (uint32_t)(p * 32));
                uint32_t f[4];
                ldmatrix_x4_t(f, base + 16384 + off);       // V hi
                mma16816(o[2*p],   ah, f[0], f[1]);
                mma16816(o[2*p],   al, f[0], f[1]);
                mma16816(o[2*p+1], ah, f[2], f[3]);
                mma16816(o[2*p+1], al, f[2], f[3]);
                ldmatrix_x4_t(f, base + 24576 + off);       // V lo
                mma16816(o[2*p],   ah, f[0], f[1]);
                mma16816(o[2*p+1], ah, f[2], f[3]);
            }
        }

        __syncthreads();                 // all warps done with buf
        if (it + 2 < 16) issueTile(it + 2);
    }

    // ---- finalize ----
    l0 += __shfl_xor_sync(0xffffffffu, l0, 1);
    l0 += __shfl_xor_sync(0xffffffffu, l0, 2);
    l1 += __shfl_xor_sync(0xffffffffu, l1, 1);
    l1 += __shfl_xor_sync(0xffffffffu, l1, 2);
    float inv0 = 1.f / l0, inv1 = 1.f / l1;

    int r0g = q0w + (L >> 2), r1g = r0g + 8;
    size_t base0 = (size_t)(b * SEQ + r0g) * HID + h * HDIM + 2 * (L & 3);
    size_t base1 = (size_t)(b * SEQ + r1g) * HID + h * HDIM + 2 * (L & 3);
#pragma unroll
    for (int nb = 0; nb < 8; nb++) {
        float x0 = o[nb][0] * inv0, y0 = o[nb][1] * inv0;
        float x1 = o[nb][2] * inv1, y1 = o[nb][3] * inv1;
        __nv_bfloat162 hp0 = __floats2bfloat162_rn(x0, y0);
        __nv_bfloat162 hp1 = __floats2bfloat162_rn(x1, y1);
        float2 hf0 = __bfloat1622float2(hp0);
        float2 hf1 = __bfloat1622float2(hp1);
        __nv_bfloat162 lp0 = __floats2bfloat162_rn(x0 - hf0.x, y0 - hf0.y);
        __nv_bfloat162 lp1 = __floats2bfloat162_rn(x1 - hf1.x, y1 - hf1.y);
        *(__nv_bfloat162*)(Chi + base0 + nb * 8) = hp0;
        *(__nv_bfloat162*)(Clo + base0 + nb * 8) = lp0;
        *(__nv_bfloat162*)(Chi + base1 + nb * 8) = hp1;
        *(__nv_bfloat162*)(Clo + base1 + nb * 8) = lp1;
    }
}

// ---------------------------------------------------------------------------
extern "C" void kernel_launch(void* const* d_in, const int* in_sizes, int n_in,
                              void* d_out, int out_size)
{
    const float* hs     = (const float*)d_in[0];
    const int*   morpho = (const int*)  d_in[1];
    const float* Wq = (const float*)d_in[2];
    const float* bq = (const float*)d_in[3];
    const float* Wk = (const float*)d_in[4];
    const float* bk = (const float*)d_in[5];
    const float* Wv = (const float*)d_in[6];
    const float* bv = (const float*)d_in[7];
    const float* Wo = (const float*)d_in[8];
    const float* bo = (const float*)d_in[9];
    float* out = (float*)d_out;

    __nv_bfloat16 *ahi, *alo, *whi, *wlo;
    __nv_bfloat16 *qhi, *qlo, *khi, *klo, *vhi, *vlo;
    cudaGetSymbolAddress((void**)&ahi, g_Ahi);
    cudaGetSymbolAddress((void**)&alo, g_Alo);
    cudaGetSymbolAddress((void**)&whi, g_Whi);
    cudaGetSymbolAddress((void**)&wlo, g_Wlo);
    cudaGetSymbolAddress((void**)&qhi, g_Qhi);
    cudaGetSymbolAddress((void**)&qlo, g_Qlo);
    cudaGetSymbolAddress((void**)&khi, g_Khi);
    cudaGetSymbolAddress((void**)&klo, g_Klo);
    cudaGetSymbolAddress((void**)&vhi, g_Vhi);
    cudaGetSymbolAddress((void**)&vlo, g_Vlo);

    static bool attr_set = false;
    if (!attr_set) {
        cudaFuncSetAttribute(gemm_qkv,
                             cudaFuncAttributeMaxDynamicSharedMemorySize, 98304);
        cudaFuncSetAttribute(gemm_out,
                             cudaFuncAttributeMaxDynamicSharedMemorySize, 98304);
        cudaFuncSetAttribute(attn_mma,
                             cudaFuncAttributeMaxDynamicSharedMemorySize, 65536);
        attr_set = true;
    }

    bias_kernel<<<dim3(BATCH, SEQ/128), 128>>>(morpho);

    split_kernel<<<MTOT*HID/1024, 256>>>((const float4*)hs,
                                         (__nv_bfloat162*)ahi, (__nv_bfloat162*)alo);

    wtrans_kernel<<<dim3(HID/32, HID/32, 4), dim3(32, 8)>>>(
        Wq, Wk, Wv, Wo, whi, wlo);

    gemm_qkv<<<dim3(HID/128, MTOT/128, 3), 256, 98304>>>(
        ahi, alo, whi, wlo, bq, bk, bv, qhi, qlo, khi, klo, vhi, vlo);

    attn_mma<<<dim3(SEQ/128, NHEAD, BATCH), 256, 65536>>>(
        qhi, qlo, khi, klo, vhi, vlo, ahi, alo);

    gemm_out<<<dim3(HID/128, MTOT/128), 256, 98304>>>(
        ahi, alo, whi + 3*(size_t)HID*HID, wlo + 3*(size_t)HID*HID, bo, out);
}

// round 13
// speedup vs baseline: 1.4097x; 1.2771x over previous
#include <cuda_runtime.h>
#include <cuda_bf16.h>
#include <cstdint>
#include <math.h>

#define BATCH 4
#define SEQ   1024
#define HID   1024
#define NHEAD 16
#define HDIM  64
#define SCALE 0.125f
#define MTOT  (BATCH*SEQ)

// ------------------------- scratch (device globals) -------------------------
__device__ __nv_bfloat16 g_Ahi[MTOT*HID];        // hi/lo split of GEMM A input
__device__ __nv_bfloat16 g_Alo[MTOT*HID];
__device__ __nv_bfloat16 g_Whi[4*HID*HID];       // transposed weights [N][K], 4 slots
__device__ __nv_bfloat16 g_Wlo[4*HID*HID];
// Q/K/V bf16 hi/lo, head-major [b][h][s][d]
__device__ __nv_bfloat16 g_Qhi[MTOT*HID];
__device__ __nv_bfloat16 g_Qlo[MTOT*HID];
__device__ __nv_bfloat16 g_Khi[MTOT*HID];
__device__ __nv_bfloat16 g_Klo[MTOT*HID];
__device__ __nv_bfloat16 g_Vhi[MTOT*HID];
__device__ __nv_bfloat16 g_Vlo[MTOT*HID];
__device__ int   g_nearest[BATCH*SEQ];
__device__ float g_colbias[BATCH*SEQ];

// ------------------------------ PTX helpers ---------------------------------
__device__ __forceinline__ uint32_t smem_u32(const void* p) {
    uint32_t a;
    asm("{ .reg .u64 t; cvta.to.shared.u64 t, %1; cvt.u32.u64 %0, t; }"
        : "=r"(a) : "l"(p));
    return a;
}

__device__ __forceinline__ void cp_async16(uint32_t saddr, const void* gaddr) {
    asm volatile("cp.async.cg.shared.global [%0], [%1], 16;"
                 :: "r"(saddr), "l"(gaddr) : "memory");
}

__device__ __forceinline__ void ldmatrix_x4(uint32_t* r, uint32_t addr) {
    asm volatile("ldmatrix.sync.aligned.m8n8.x4.shared.b16 {%0,%1,%2,%3}, [%4];"
                 : "=r"(r[0]), "=r"(r[1]), "=r"(r[2]), "=r"(r[3]) : "r"(addr));
}

__device__ __forceinline__ void ldmatrix_x4_t(uint32_t* r, uint32_t addr) {
    asm volatile("ldmatrix.sync.aligned.m8n8.x4.trans.shared.b16 {%0,%1,%2,%3}, [%4];"
                 : "=r"(r[0]), "=r"(r[1]), "=r"(r[2]), "=r"(r[3]) : "r"(addr));
}

__device__ __forceinline__ void mma16816(float* d, const uint32_t* a,
                                         uint32_t b0, uint32_t b1) {
    asm volatile(
        "mma.sync.aligned.m16n8k16.row.col.f32.bf16.bf16.f32 "
        "{%0,%1,%2,%3}, {%4,%5,%6,%7}, {%8,%9}, {%0,%1,%2,%3};"
        : "+f"(d[0]), "+f"(d[1]), "+f"(d[2]), "+f"(d[3])
        : "r"(a[0]), "r"(a[1]), "r"(a[2]), "r"(a[3]), "r"(b0), "r"(b1));
}

#define SWZ(x) ((x) ^ (((x) >> 3) & 0x70))

__device__ __forceinline__ uint32_t pack_bf2(float x, float y) {
    __nv_bfloat162 h = __floats2bfloat162_rn(x, y);
    return *(uint32_t*)&h;
}

// ---------------------------------------------------------------------------
// Morphological bias precompute (parallelized: 32 blocks)
// ---------------------------------------------------------------------------
__global__ void bias_kernel(const int* __restrict__ morpho)
{
    int b = blockIdx.x;
    __shared__ int types[SEQ];
    for (int i = threadIdx.x; i < SEQ; i += blockDim.x)
        types[i] = morpho[b*SEQ + i];
    __syncthreads();
    int q = blockIdx.y * 128 + threadIdx.x;
    int best = -1;
    int bestd = 1 << 30;
    for (int j = 0; j < SEQ; j++) {
        if (types[j] == 2) {
            int d = abs(q - j);
            if (d < bestd) { bestd = d; best = j; }
        }
    }
    g_nearest[b*SEQ + q] = best;
    int t = types[q];
    float cb = 0.0f;
    if (t == 0) cb = 0.75f;
    else if (t == 1) cb = 0.36f;
    g_colbias[b*SEQ + q] = cb;
}

// ---------------------------------------------------------------------------
// fp32 -> bf16 hi/lo split (row-major, vectorized by 4)
// ---------------------------------------------------------------------------
__global__ void __launch_bounds__(256) split_kernel(
    const float4* __restrict__ src, __nv_bfloat162* __restrict__ hi,
    __nv_bfloat162* __restrict__ lo)
{
    int i = blockIdx.x * 256 + threadIdx.x;
    float4 v = src[i];
    __nv_bfloat16 h0 = __float2bfloat16(v.x);
    __nv_bfloat16 h1 = __float2bfloat16(v.y);
    __nv_bfloat16 h2 = __float2bfloat16(v.z);
    __nv_bfloat16 h3 = __float2bfloat16(v.w);
    __nv_bfloat162 ha; ha.x = h0; ha.y = h1;
    __nv_bfloat162 hb; hb.x = h2; hb.y = h3;
    hi[2*i] = ha; hi[2*i+1] = hb;
    __nv_bfloat162 la, lb;
    la.x = __float2bfloat16(v.x - __bfloat162float(h0));
    la.y = __float2bfloat16(v.y - __bfloat162float(h1));
    lb.x = __float2bfloat16(v.z - __bfloat162float(h2));
    lb.y = __float2bfloat16(v.w - __bfloat162float(h3));
    lo[2*i] = la; lo[2*i+1] = lb;
}

// ---------------------------------------------------------------------------
// W [K][N] fp32 -> Wt hi/lo [N][K] bf16 (transpose + split), z = weight slot
// ---------------------------------------------------------------------------
__global__ void wtrans_kernel(const float* __restrict__ W0,
                              const float* __restrict__ W1,
                              const float* __restrict__ W2,
                              const float* __restrict__ W3,
                              __nv_bfloat16* __restrict__ hiB,
                              __nv_bfloat16* __restrict__ loB)
{
    int z = blockIdx.z;
    const float* W = (z == 0) ? W0 : (z == 1) ? W1 : (z == 2) ? W2 : W3;
    __nv_bfloat16* hi = hiB + (size_t)z * HID * HID;
    __nv_bfloat16* lo = loB + (size_t)z * HID * HID;

    __shared__ float t[32][33];
    int n0 = blockIdx.x * 32, k0 = blockIdx.y * 32;
    int c = threadIdx.x, r0 = threadIdx.y;        // 32 x 8
#pragma unroll
    for (int i = 0; i < 4; i++)
        t[r0 + 8*i][c] = W[(size_t)(k0 + r0 + 8*i) * HID + n0 + c];
    __syncthreads();
#pragma unroll
    for (int i = 0; i < 4; i++) {
        int rr = r0 + 8*i;
        float v = t[c][rr];
        __nv_bfloat16 h = __float2bfloat16(v);
        hi[(size_t)(n0 + rr) * HID + k0 + c] = h;
        lo[(size_t)(n0 + rr) * HID + k0 + c] =
            __float2bfloat16(v - __bfloat162float(h));
    }
}

// ---------------------------------------------------------------------------
// GEMM mainloop: 128x128 CTA tile, 4 warps (2x2), warp tile 64x64.
// 3 sequential K-passes (RAW distance 32), 3-stage pipeline, depth 2.
// Per ks-step per warp: 8 ldmatrix -> 32 MMAs (4.0 MMA/ldsm).
// ---------------------------------------------------------------------------
__device__ __forceinline__ void gemm_core(
    const __nv_bfloat16* __restrict__ Ahi, const __nv_bfloat16* __restrict__ Alo,
    const __nv_bfloat16* __restrict__ Bhi, const __nv_bfloat16* __restrict__ Blo,
    int bm, int bn, uint32_t sbase, float acc[4][8][4])
{
    const int tid = threadIdx.x;          // 0..127
    const int L = tid & 31;
    const int wid = tid >> 5;             // 0..3
    const int wm = wid >> 1;              // 0..1 -> rows wm*64
    const int wn = wid & 1;               // 0..1 -> cols wn*64

    const int ldrow = tid >> 3;           // 0..15
    const int ldcu  = tid & 7;            // 16B-unit col

    uint32_t aRow = (uint32_t)(wm * 64 + (L & 15)) * 128 + ((L >> 4) << 4);
    uint32_t bRow = (uint32_t)(wn * 64 + (L & 7) + ((L >> 4) & 1) * 8) * 128
                  + (((L >> 3) & 1) << 4);

    auto loadChunk = [&](int it) {
        int pass = it >> 4;
        int k0 = (it & 15) << 6;
        int buf = it % 3;
        const __nv_bfloat16* Ap = (pass == 2) ? Alo : Ahi;
        const __nv_bfloat16* Bp = (pass == 1) ? Blo : Bhi;
        uint32_t sa = sbase + (uint32_t)buf * 16384;
        uint32_t sb = sbase + 49152 + (uint32_t)buf * 16384;
#pragma unroll
        for (int i = 0; i < 8; i++) {
            int row = ldrow + i * 16;
            uint32_t sw = SWZ((uint32_t)(row * 128) + (ldcu << 4));
            cp_async16(sa + sw, Ap + (size_t)(bm + row) * HID + k0 + (ldcu << 3));
            cp_async16(sb + sw, Bp + (size_t)(bn + row) * HID + k0 + (ldcu << 3));
        }
    };

    loadChunk(0);
    asm volatile("cp.async.commit_group;" ::: "memory");
    loadChunk(1);
    asm volatile("cp.async.commit_group;" ::: "memory");

    for (int it = 0; it < 48; it++) {
        if (it + 1 < 48)
            asm volatile("cp.async.wait_group 1;" ::: "memory");
        else
            asm volatile("cp.async.wait_group 0;" ::: "memory");
        __syncthreads();
        if (it + 2 < 48) {
            loadChunk(it + 2);
            asm volatile("cp.async.commit_group;" ::: "memory");
        }

        int buf = it % 3;
        uint32_t sa = sbase + (uint32_t)buf * 16384;
        uint32_t sb = sbase + 49152 + (uint32_t)buf * 16384;

#pragma unroll
        for (int ks = 0; ks < 4; ks++) {
            uint32_t a[4][4], b[4][4];
#pragma unroll
            for (int mt = 0; mt < 4; mt++) {
                uint32_t off = aRow + (uint32_t)(mt * 16 * 128) + (uint32_t)(ks * 32);
                ldmatrix_x4(a[mt], sa + SWZ(off));
            }
#pragma unroll
            for (int p = 0; p < 4; p++) {
                uint32_t off = bRow + (uint32_t)(p * 16 * 128) + (uint32_t)(ks * 32);
                ldmatrix_x4(b[p], sb + SWZ(off));
            }
#pragma unroll
            for (int mt = 0; mt < 4; mt++)
#pragma unroll
                for (int nt = 0; nt < 8; nt++)
                    mma16816(acc[mt][nt], a[mt],
                             b[nt >> 1][(nt & 1) * 2], b[nt >> 1][(nt & 1) * 2 + 1]);
        }
    }
}

// ---------------------------------------------------------------------------
// Fused QKV projection: blockIdx.z in {0,1,2} selects weight/bias/dest.
// ---------------------------------------------------------------------------
__global__ void __launch_bounds__(128, 2) gemm_qkv(
    const __nv_bfloat16* __restrict__ Ahi, const __nv_bfloat16* __restrict__ Alo,
    const __nv_bfloat16* __restrict__ WhiB, const __nv_bfloat16* __restrict__ WloB,
    const float* __restrict__ bq, const float* __restrict__ bk,
    const float* __restrict__ bv,
    __nv_bfloat16* __restrict__ qhi, __nv_bfloat16* __restrict__ qlo,
    __nv_bfloat16* __restrict__ khi, __nv_bfloat16* __restrict__ klo,
    __nv_bfloat16* __restrict__ vhi, __nv_bfloat16* __restrict__ vlo)
{
    extern __shared__ __align__(1024) char smem[];
    const int z = blockIdx.z;
    const __nv_bfloat16* Bhi = WhiB + (size_t)z * HID * HID;
    const __nv_bfloat16* Blo = WloB + (size_t)z * HID * HID;
    const float* bias = (z == 0) ? bq : (z == 1) ? bk : bv;
    __nv_bfloat16* Chi = (z == 0) ? qhi : (z == 1) ? khi : vhi;
    __nv_bfloat16* Clo = (z == 0) ? qlo : (z == 1) ? klo : vlo;
    const float scale = (z == 0) ? SCALE : 1.0f;

    const int bm = blockIdx.y * 128, bn = blockIdx.x * 128;

    float acc[4][8][4];
#pragma unroll
    for (int i = 0; i < 4; i++)
#pragma unroll
        for (int j = 0; j < 8; j++)
#pragma unroll
            for (int k = 0; k < 4; k++) acc[i][j][k] = 0.f;

    gemm_core(Ahi, Alo, Bhi, Blo, bm, bn, smem_u32(smem), acc);

    const int tid = threadIdx.x, L = tid & 31, wid = tid >> 5;
    const int wm = wid >> 1, wn = wid & 1;
    const int r = L >> 2, c2 = (L & 3) * 2;
#pragma unroll
    for (int mt = 0; mt < 4; mt++) {
        int gm0 = bm + wm * 64 + mt * 16 + r;
#pragma unroll
        for (int nt = 0; nt < 8; nt++) {
            int gn = bn + wn * 64 + nt * 8 + c2;
            float b0 = bias[gn], b1 = bias[gn + 1];
            float v00 = (acc[mt][nt][0] + b0) * scale;
            float v01 = (acc[mt][nt][1] + b1) * scale;
            float v10 = (acc[mt][nt][2] + b0) * scale;
            float v11 = (acc[mt][nt][3] + b1) * scale;
            int hh = gn >> 6, d = gn & 63;
#pragma unroll
            for (int half = 0; half < 2; half++) {
                int gm = gm0 + half * 8;
                float x = half ? v10 : v00, y = half ? v11 : v01;
                int bb = gm >> 10, s = gm & 1023;
                size_t idx = ((size_t)((bb * NHEAD + hh) * SEQ) + s) * HDIM + d;
                __nv_bfloat162 hp = __floats2bfloat162_rn(x, y);
                float2 hf = __bfloat1622float2(hp);
                __nv_bfloat162 lp = __floats2bfloat162_rn(x - hf.x, y - hf.y);
                *(__nv_bfloat162*)(Chi + idx) = hp;
                *(__nv_bfloat162*)(Clo + idx) = lp;
            }
        }
    }
}

// ---------------------------------------------------------------------------
// Output projection: fp32 row-major destination.
// ---------------------------------------------------------------------------
__global__ void __launch_bounds__(128, 2) gemm_out(
    const __nv_bfloat16* __restrict__ Ahi, const __nv_bfloat16* __restrict__ Alo,
    const __nv_bfloat16* __restrict__ Bhi, const __nv_bfloat16* __restrict__ Blo,
    const float* __restrict__ bias, float* __restrict__ C)
{
    extern __shared__ __align__(1024) char smem[];
    const int bm = blockIdx.y * 128, bn = blockIdx.x * 128;

    float acc[4][8][4];
#pragma unroll
    for (int i = 0; i < 4; i++)
#pragma unroll
        for (int j = 0; j < 8; j++)
#pragma unroll
            for (int k = 0; k < 4; k++) acc[i][j][k] = 0.f;

    gemm_core(Ahi, Alo, Bhi, Blo, bm, bn, smem_u32(smem), acc);

    const int tid = threadIdx.x, L = tid & 31, wid = tid >> 5;
    const int wm = wid >> 1, wn = wid & 1;
    const int r = L >> 2, c2 = (L & 3) * 2;
#pragma unroll
    for (int mt = 0; mt < 4; mt++) {
        int gm0 = bm + wm * 64 + mt * 16 + r;
#pragma unroll
        for (int nt = 0; nt < 8; nt++) {
            int gn = bn + wn * 64 + nt * 8 + c2;
            float b0 = bias[gn], b1 = bias[gn + 1];
            float2 w0, w1;
            w0.x = acc[mt][nt][0] + b0; w0.y = acc[mt][nt][1] + b1;
            w1.x = acc[mt][nt][2] + b0; w1.y = acc[mt][nt][3] + b1;
            *(float2*)(C + (size_t)gm0 * HID + gn) = w0;
            *(float2*)(C + (size_t)(gm0 + 8) * HID + gn) = w1;
        }
    }
}

// ---------------------------------------------------------------------------
// Tensor-core flash attention, bf16-split, double-buffered KV tiles.
// CTA = 128 q-rows x one (b,h); 8 warps; KV tile = 64. 64KB dynamic smem.
// ---------------------------------------------------------------------------
__global__ void __launch_bounds__(256) attn_mma(
    const __nv_bfloat16* __restrict__ Qhi, const __nv_bfloat16* __restrict__ Qlo,
    const __nv_bfloat16* __restrict__ Khi, const __nv_bfloat16* __restrict__ Klo,
    const __nv_bfloat16* __restrict__ Vhi, const __nv_bfloat16* __restrict__ Vlo,
    __nv_bfloat16* __restrict__ Chi, __nv_bfloat16* __restrict__ Clo)
{
    extern __shared__ __align__(1024) char smem[];   // 64 KB: buf0/buf1 32KB each
    __shared__ float sCB[2][64];

    const int tid = threadIdx.x, L = tid & 31, wid = tid >> 5;
    const int b = blockIdx.z, h = blockIdx.y;
    const int qcta = blockIdx.x * 128;
    const int q0w = qcta + wid * 16;
    const uint32_t sb = smem_u32(smem);
    const size_t headbase = ((size_t)(b * NHEAD + h)) * SEQ;

    // ---- stage Q tile (128x64 hi+lo) through buf0 into A-fragments ----
    {
        const __nv_bfloat16* qh = Qhi + (headbase + qcta) * HDIM;
        const __nv_bfloat16* ql = Qlo + (headbase + qcta) * HDIM;
#pragma unroll
        for (int i = 0; i < 4; i++) {
            int u = tid + i * 256;
            int row = u >> 3, cu = u & 7;
            uint32_t sw = SWZ((uint32_t)(row * 128 + cu * 16));
            cp_async16(sb + sw, qh + (size_t)row * HDIM + cu * 8);
            cp_async16(sb + 16384 + sw, ql + (size_t)row * HDIM + cu * 8);
        }
        asm volatile("cp.async.commit_group;" ::: "memory");
        asm volatile("cp.async.wait_group 0;" ::: "memory");
        __syncthreads();
    }
    uint32_t qh[4][4], ql[4][4];
    {
        uint32_t base = (uint32_t)((wid * 16 + (L & 15)) * 128 + ((L >> 4) << 4));
#pragma unroll
        for (int ks = 0; ks < 4; ks++) {
            uint32_t off = SWZ(base + ks * 32);
            ldmatrix_x4(qh[ks], sb + off);
            ldmatrix_x4(ql[ks], sb + 16384 + off);
        }
    }
    __syncthreads();   // Q fully consumed; buffers free for KV

    const int nr0 = g_nearest[b * SEQ + q0w + (L >> 2)];
    const int nr1 = g_nearest[b * SEQ + q0w + (L >> 2) + 8];

    float o[8][4];
#pragma unroll
    for (int i = 0; i < 8; i++)
#pragma unroll
        for (int j = 0; j < 4; j++) o[i][j] = 0.f;
    float m0 = -1e30f, m1 = -1e30f, l0 = 0.f, l1 = 0.f;

    uint32_t kBase = (uint32_t)((L & 7) + ((L >> 4) & 1) * 8) * 128
                   + (((L >> 3) & 1) << 4);
    uint32_t vBase = (uint32_t)((L & 7) + ((L >> 3) & 1) * 8) * 128
                   + ((L >> 4) << 4);

    auto issueTile = [&](int t) {
        int buf = t & 1;
        uint32_t base = sb + buf * 32768;
        int kt = t * 64;
        const __nv_bfloat16* kh = Khi + (headbase + kt) * HDIM;
        const __nv_bfloat16* kl = Klo + (headbase + kt) * HDIM;
        const __nv_bfloat16* vh = Vhi + (headbase + kt) * HDIM;
        const __nv_bfloat16* vl = Vlo + (headbase + kt) * HDIM;
#pragma unroll
        for (int i = 0; i < 2; i++) {
            int u = tid + i * 256;
            int row = u >> 3, cu = u & 7;
            uint32_t sw = SWZ((uint32_t)(row * 128 + cu * 16));
            size_t g = (size_t)row * HDIM + cu * 8;
            cp_async16(base + sw,         kh + g);
            cp_async16(base +  8192 + sw, kl + g);
            cp_async16(base + 16384 + sw, vh + g);
            cp_async16(base + 24576 + sw, vl + g);
        }
        if (tid < 64) sCB[buf][tid] = g_colbias[b * SEQ + kt + tid];
        asm volatile("cp.async.commit_group;" ::: "memory");
    };

    issueTile(0);
    issueTile(1);

    for (int it = 0; it < 16; it++) {
        if (it + 1 < 16)
            asm volatile("cp.async.wait_group 1;" ::: "memory");
        else
            asm volatile("cp.async.wait_group 0;" ::: "memory");
        __syncthreads();

        const int buf = it & 1;
        const uint32_t base = sb + buf * 32768;
        const int kt = it * 64;

        // ---- S = Qh*Kh + Qh*Kl + Ql*Kh ----
        float s[8][4];
#pragma unroll
        for (int i = 0; i < 8; i++)
#pragma unroll
            for (int j = 0; j < 4; j++) s[i][j] = 0.f;

#pragma unroll
        for (int ks = 0; ks < 4; ks++) {
#pragma unroll
            for (int p = 0; p < 4; p++) {
                uint32_t off = SWZ(kBase + (uint32_t)(p * 16 * 128) + (uint32_t)(ks * 32));
                uint32_t f[4];
                ldmatrix_x4(f, base + off);                 // K hi
                mma16816(s[2*p],   qh[ks], f[0], f[1]);
                mma16816(s[2*p],   ql[ks], f[0], f[1]);
                mma16816(s[2*p+1], qh[ks], f[2], f[3]);
                mma16816(s[2*p+1], ql[ks], f[2], f[3]);
                ldmatrix_x4(f, base + 8192 + off);          // K lo
                mma16816(s[2*p],   qh[ks], f[0], f[1]);
                mma16816(s[2*p+1], qh[ks], f[2], f[3]);
            }
        }

        // ---- bias + online softmax ----
        int colb = kt + 2 * (L & 3);
        float t0 = -1e30f, t1 = -1e30f;
#pragma unroll
        for (int nb = 0; nb < 8; nb++) {
            float c0 = sCB[buf][nb * 8 + 2 * (L & 3)];
            float c1 = sCB[buf][nb * 8 + 2 * (L & 3) + 1];
            int g0 = colb + nb * 8, g1 = g0 + 1;
            s[nb][0] += c0 + (g0 == nr0 ? 2.f : 0.f);
            s[nb][1] += c1 + (g1 == nr0 ? 2.f : 0.f);
            s[nb][2] += c0 + (g0 == nr1 ? 2.f : 0.f);
            s[nb][3] += c1 + (g1 == nr1 ? 2.f : 0.f);
            t0 = fmaxf(t0, fmaxf(s[nb][0], s[nb][1]));
            t1 = fmaxf(t1, fmaxf(s[nb][2], s[nb][3]));
        }
        t0 = fmaxf(t0, __shfl_xor_sync(0xffffffffu, t0, 1));
        t0 = fmaxf(t0, __shfl_xor_sync(0xffffffffu, t0, 2));
        t1 = fmaxf(t1, __shfl_xor_sync(0xffffffffu, t1, 1));
        t1 = fmaxf(t1, __shfl_xor_sync(0xffffffffu, t1, 2));
        float nm0 = fmaxf(m0, t0), nm1 = fmaxf(m1, t1);
        float cr0 = __expf(m0 - nm0), cr1 = __expf(m1 - nm1);
        m0 = nm0; m1 = nm1;
        l0 *= cr0; l1 *= cr1;
#pragma unroll
        for (int nb = 0; nb < 8; nb++) {
            o[nb][0] *= cr0; o[nb][1] *= cr0;
            o[nb][2] *= cr1; o[nb][3] *= cr1;
            s[nb][0] = __expf(s[nb][0] - m0); l0 += s[nb][0];
            s[nb][1] = __expf(s[nb][1] - m0); l0 += s[nb][1];
            s[nb][2] = __expf(s[nb][2] - m1); l1 += s[nb][2];
            s[nb][3] = __expf(s[nb][3] - m1); l1 += s[nb][3];
        }

        // ---- O += Ph*Vh + Ph*Vl + Pl*Vh ----
#pragma unroll
        for (int ks = 0; ks < 4; ks++) {
            uint32_t ah[4], al[4];
#pragma unroll
            for (int half = 0; half < 2; half++) {
                int nb = 2 * ks + half;
                __nv_bfloat162 h01 = __floats2bfloat162_rn(s[nb][0], s[nb][1]);
                __nv_bfloat162 h23 = __floats2bfloat162_rn(s[nb][2], s[nb][3]);
                float2 f01 = __bfloat1622float2(h01);
                float2 f23 = __bfloat1622float2(h23);
                ah[2*half]   = *(uint32_t*)&h01;
                ah[2*half+1] = *(uint32_t*)&h23;
                al[2*half]   = pack_bf2(s[nb][0] - f01.x, s[nb][1] - f01.y);
                al[2*half+1] = pack_bf2(s[nb][2] - f23.x, s[nb][3] - f23.y);
            }
#pragma unroll
            for (int p = 0; p < 4; p++) {
                uint32_t off = SWZ(vBase + (uint32_t)(ks * 16 * 128) + (uint32_t)(p * 32));
                uint32_t f[4];
                ldmatrix_x4_t(f, base + 16384 + off);       // V hi
                mma16816(o[2*p],   ah, f[0], f[1]);
                mma16816(o[2*p],   al, f[0], f[1]);
                mma16816(o[2*p+1], ah, f[2], f[3]);
                mma16816(o[2*p+1], al, f[2], f[3]);
                ldmatrix_x4_t(f, base + 24576 + off);       // V lo
                mma16816(o[2*p],   ah, f[0], f[1]);
                mma16816(o[2*p+1], ah, f[2], f[3]);
            }
        }

        __syncthreads();                 // all warps done with buf
        if (it + 2 < 16) issueTile(it + 2);
    }

    // ---- finalize ----
    l0 += __shfl_xor_sync(0xffffffffu, l0, 1);
    l0 += __shfl_xor_sync(0xffffffffu, l0, 2);
    l1 += __shfl_xor_sync(0xffffffffu, l1, 1);
    l1 += __shfl_xor_sync(0xffffffffu, l1, 2);
    float inv0 = 1.f / l0, inv1 = 1.f / l1;

    int r0g = q0w + (L >> 2), r1g = r0g + 8;
    size_t base0 = (size_t)(b * SEQ + r0g) * HID + h * HDIM + 2 * (L & 3);
    size_t base1 = (size_t)(b * SEQ + r1g) * HID + h * HDIM + 2 * (L & 3);
#pragma unroll
    for (int nb = 0; nb < 8; nb++) {
        float x0 = o[nb][0] * inv0, y0 = o[nb][1] * inv0;
        float x1 = o[nb][2] * inv1, y1 = o[nb][3] * inv1;
        __nv_bfloat162 hp0 = __floats2bfloat162_rn(x0, y0);
        __nv_bfloat162 hp1 = __floats2bfloat162_rn(x1, y1);
        float2 hf0 = __bfloat1622float2(hp0);
        float2 hf1 = __bfloat1622float2(hp1);
        __nv_bfloat162 lp0 = __floats2bfloat162_rn(x0 - hf0.x, y0 - hf0.y);
        __nv_bfloat162 lp1 = __floats2bfloat162_rn(x1 - hf1.x, y1 - hf1.y);
        *(__nv_bfloat162*)(Chi + base0 + nb * 8) = hp0;
        *(__nv_bfloat162*)(Clo + base0 + nb * 8) = lp0;
        *(__nv_bfloat162*)(Chi + base1 + nb * 8) = hp1;
        *(__nv_bfloat162*)(Clo + base1 + nb * 8) = lp1;
    }
}

// ---------------------------------------------------------------------------
extern "C" void kernel_launch(void* const* d_in, const int* in_sizes, int n_in,
                              void* d_out, int out_size)
{
    const float* hs     = (const float*)d_in[0];
    const int*   morpho = (const int*)  d_in[1];
    const float* Wq = (const float*)d_in[2];
    const float* bq = (const float*)d_in[3];
    const float* Wk = (const float*)d_in[4];
    const float* bk = (const float*)d_in[5];
    const float* Wv = (const float*)d_in[6];
    const float* bv = (const float*)d_in[7];
    const float* Wo = (const float*)d_in[8];
    const float* bo = (const float*)d_in[9];
    float* out = (float*)d_out;

    __nv_bfloat16 *ahi, *alo, *whi, *wlo;
    __nv_bfloat16 *qhi, *qlo, *khi, *klo, *vhi, *vlo;
    cudaGetSymbolAddress((void**)&ahi, g_Ahi);
    cudaGetSymbolAddress((void**)&alo, g_Alo);
    cudaGetSymbolAddress((void**)&whi, g_Whi);
    cudaGetSymbolAddress((void**)&wlo, g_Wlo);
    cudaGetSymbolAddress((void**)&qhi, g_Qhi);
    cudaGetSymbolAddress((void**)&qlo, g_Qlo);
    cudaGetSymbolAddress((void**)&khi, g_Khi);
    cudaGetSymbolAddress((void**)&klo, g_Klo);
    cudaGetSymbolAddress((void**)&vhi, g_Vhi);
    cudaGetSymbolAddress((void**)&vlo, g_Vlo);

    static bool attr_set = false;
    if (!attr_set) {
        cudaFuncSetAttribute(gemm_qkv,
                             cudaFuncAttributeMaxDynamicSharedMemorySize, 98304);
        cudaFuncSetAttribute(gemm_out,
                             cudaFuncAttributeMaxDynamicSharedMemorySize, 98304);
        cudaFuncSetAttribute(attn_mma,
                             cudaFuncAttributeMaxDynamicSharedMemorySize, 65536);
        attr_set = true;
    }

    bias_kernel<<<dim3(BATCH, SEQ/128), 128>>>(morpho);

    split_kernel<<<MTOT*HID/1024, 256>>>((const float4*)hs,
                                         (__nv_bfloat162*)ahi, (__nv_bfloat162*)alo);

    wtrans_kernel<<<dim3(HID/32, HID/32, 4), dim3(32, 8)>>>(
        Wq, Wk, Wv, Wo, whi, wlo);

    gemm_qkv<<<dim3(HID/128, MTOT/128, 3), 128, 98304>>>(
        ahi, alo, whi, wlo, bq, bk, bv, qhi, qlo, khi, klo, vhi, vlo);

    attn_mma<<<dim3(SEQ/128, NHEAD, BATCH), 256, 65536>>>(
        qhi, qlo, khi, klo, vhi, vlo, ahi, alo);

    gemm_out<<<dim3(HID/128, MTOT/128), 128, 98304>>>(
        ahi, alo, whi + 3*(size_t)HID*HID, wlo + 3*(size_t)HID*HID, bo, out);
}

// round 15
// speedup vs baseline: 1.4266x; 1.0120x over previous
#include <cuda_runtime.h>
#include <cuda_bf16.h>
#include <cstdint>
#include <math.h>

#define BATCH 4
#define SEQ   1024
#define HID   1024
#define NHEAD 16
#define HDIM  64
#define SCALE 0.125f
#define MTOT  (BATCH*SEQ)

// ------------------------- scratch (device globals) -------------------------
__device__ __nv_bfloat16 g_Ahi[MTOT*HID];
__device__ __nv_bfloat16 g_Alo[MTOT*HID];
__device__ __nv_bfloat16 g_Whi[4*HID*HID];
__device__ __nv_bfloat16 g_Wlo[4*HID*HID];
__device__ __nv_bfloat16 g_Qhi[MTOT*HID];
__device__ __nv_bfloat16 g_Qlo[MTOT*HID];
__device__ __nv_bfloat16 g_Khi[MTOT*HID];
__device__ __nv_bfloat16 g_Klo[MTOT*HID];
__device__ __nv_bfloat16 g_Vhi[MTOT*HID];
__device__ __nv_bfloat16 g_Vlo[MTOT*HID];
__device__ int   g_nearest[BATCH*SEQ];
__device__ float g_colbias[BATCH*SEQ];

// ------------------------------ PTX helpers ---------------------------------
__device__ __forceinline__ uint32_t smem_u32(const void* p) {
    uint32_t a;
    asm("{ .reg .u64 t; cvta.to.shared.u64 t, %1; cvt.u32.u64 %0, t; }"
        : "=r"(a) : "l"(p));
    return a;
}

__device__ __forceinline__ void cp_async16(uint32_t saddr, const void* gaddr) {
    asm volatile("cp.async.cg.shared.global [%0], [%1], 16;"
                 :: "r"(saddr), "l"(gaddr) : "memory");
}

__device__ __forceinline__ void ldmatrix_x4(uint32_t* r, uint32_t addr) {
    asm volatile("ldmatrix.sync.aligned.m8n8.x4.shared.b16 {%0,%1,%2,%3}, [%4];"
                 : "=r"(r[0]), "=r"(r[1]), "=r"(r[2]), "=r"(r[3]) : "r"(addr));
}

__device__ __forceinline__ void ldmatrix_x4_t(uint32_t* r, uint32_t addr) {
    asm volatile("ldmatrix.sync.aligned.m8n8.x4.trans.shared.b16 {%0,%1,%2,%3}, [%4];"
                 : "=r"(r[0]), "=r"(r[1]), "=r"(r[2]), "=r"(r[3]) : "r"(addr));
}

__device__ __forceinline__ void mma16816(float* d, const uint32_t* a,
                                         uint32_t b0, uint32_t b1) {
    asm volatile(
        "mma.sync.aligned.m16n8k16.row.col.f32.bf16.bf16.f32 "
        "{%0,%1,%2,%3}, {%4,%5,%6,%7}, {%8,%9}, {%0,%1,%2,%3};"
        : "+f"(d[0]), "+f"(d[1]), "+f"(d[2]), "+f"(d[3])
        : "r"(a[0]), "r"(a[1]), "r"(a[2]), "r"(a[3]), "r"(b0), "r"(b1));
}

#define SWZ(x) ((x) ^ (((x) >> 3) & 0x70))

__device__ __forceinline__ uint32_t pack_bf2(float x, float y) {
    __nv_bfloat162 h = __floats2bfloat162_rn(x, y);
    return *(uint32_t*)&h;
}

// ---------------------------------------------------------------------------
__global__ void bias_kernel(const int* __restrict__ morpho)
{
    int b = blockIdx.x;
    __shared__ int types[SEQ];
    for (int i = threadIdx.x; i < SEQ; i += blockDim.x)
        types[i] = morpho[b*SEQ + i];
    __syncthreads();
    int q = blockIdx.y * 128 + threadIdx.x;
    int best = -1;
    int bestd = 1 << 30;
    for (int j = 0; j < SEQ; j++) {
        if (types[j] == 2) {
            int d = abs(q - j);
            if (d < bestd) { bestd = d; best = j; }
        }
    }
    g_nearest[b*SEQ + q] = best;
    int t = types[q];
    float cb = 0.0f;
    if (t == 0) cb = 0.75f;
    else if (t == 1) cb = 0.36f;
    g_colbias[b*SEQ + q] = cb;
}

// ---------------------------------------------------------------------------
__global__ void __launch_bounds__(256) split_kernel(
    const float4* __restrict__ src, __nv_bfloat162* __restrict__ hi,
    __nv_bfloat162* __restrict__ lo)
{
    int i = blockIdx.x * 256 + threadIdx.x;
    float4 v = src[i];
    __nv_bfloat16 h0 = __float2bfloat16(v.x);
    __nv_bfloat16 h1 = __float2bfloat16(v.y);
    __nv_bfloat16 h2 = __float2bfloat16(v.z);
    __nv_bfloat16 h3 = __float2bfloat16(v.w);
    __nv_bfloat162 ha; ha.x = h0; ha.y = h1;
    __nv_bfloat162 hb; hb.x = h2; hb.y = h3;
    hi[2*i] = ha; hi[2*i+1] = hb;
    __nv_bfloat162 la, lb;
    la.x = __float2bfloat16(v.x - __bfloat162float(h0));
    la.y = __float2bfloat16(v.y - __bfloat162float(h1));
    lb.x = __float2bfloat16(v.z - __bfloat162float(h2));
    lb.y = __float2bfloat16(v.w - __bfloat162float(h3));
    lo[2*i] = la; lo[2*i+1] = lb;
}

// ---------------------------------------------------------------------------
__global__ void wtrans_kernel(const float* __restrict__ W0,
                              const float* __restrict__ W1,
                              const float* __restrict__ W2,
                              const float* __restrict__ W3,
                              __nv_bfloat16* __restrict__ hiB,
                              __nv_bfloat16* __restrict__ loB)
{
    int z = blockIdx.z;
    const float* W = (z == 0) ? W0 : (z == 1) ? W1 : (z == 2) ? W2 : W3;
    __nv_bfloat16* hi = hiB + (size_t)z * HID * HID;
    __nv_bfloat16* lo = loB + (size_t)z * HID * HID;

    __shared__ float t[32][33];
    int n0 = blockIdx.x * 32, k0 = blockIdx.y * 32;
    int c = threadIdx.x, r0 = threadIdx.y;
#pragma unroll
    for (int i = 0; i < 4; i++)
        t[r0 + 8*i][c] = W[(size_t)(k0 + r0 + 8*i) * HID + n0 + c];
    __syncthreads();
#pragma unroll
    for (int i = 0; i < 4; i++) {
        int rr = r0 + 8*i;
        float v = t[c][rr];
        __nv_bfloat16 h = __float2bfloat16(v);
        hi[(size_t)(n0 + rr) * HID + k0 + c] = h;
        lo[(size_t)(n0 + rr) * HID + k0 + c] =
            __float2bfloat16(v - __bfloat162float(h));
    }
}

// ---------------------------------------------------------------------------
// GEMM mainloop: 128x128 CTA tile, 4 warps (2x2), warp tile 64x64.
// ---------------------------------------------------------------------------
__device__ __forceinline__ void gemm_core(
    const __nv_bfloat16* __restrict__ Ahi, const __nv_bfloat16* __restrict__ Alo,
    const __nv_bfloat16* __restrict__ Bhi, const __nv_bfloat16* __restrict__ Blo,
    int bm, int bn, uint32_t sbase, float acc[4][8][4])
{
    const int tid = threadIdx.x;
    const int L = tid & 31;
    const int wid = tid >> 5;
    const int wm = wid >> 1;
    const int wn = wid & 1;

    const int ldrow = tid >> 3;
    const int ldcu  = tid & 7;

    uint32_t aRow = (uint32_t)(wm * 64 + (L & 15)) * 128 + ((L >> 4) << 4);
    uint32_t bRow = (uint32_t)(wn * 64 + (L & 7) + ((L >> 4) & 1) * 8) * 128
                  + (((L >> 3) & 1) << 4);

    auto loadChunk = [&](int it) {
        int pass = it >> 4;
        int k0 = (it & 15) << 6;
        int buf = it % 3;
        const __nv_bfloat16* Ap = (pass == 2) ? Alo : Ahi;
        const __nv_bfloat16* Bp = (pass == 1) ? Blo : Bhi;
        uint32_t sa = sbase + (uint32_t)buf * 16384;
        uint32_t sb = sbase + 49152 + (uint32_t)buf * 16384;
#pragma unroll
        for (int i = 0; i < 8; i++) {
            int row = ldrow + i * 16;
            uint32_t sw = SWZ((uint32_t)(row * 128) + (ldcu << 4));
            cp_async16(sa + sw, Ap + (size_t)(bm + row) * HID + k0 + (ldcu << 3));
            cp_async16(sb + sw, Bp + (size_t)(bn + row) * HID + k0 + (ldcu << 3));
        }
    };

    loadChunk(0);
    asm volatile("cp.async.commit_group;" ::: "memory");
    loadChunk(1);
    asm volatile("cp.async.commit_group;" ::: "memory");

    for (int it = 0; it < 48; it++) {
        if (it + 1 < 48)
            asm volatile("cp.async.wait_group 1;" ::: "memory");
        else
            asm volatile("cp.async.wait_group 0;" ::: "memory");
        __syncthreads();
        if (it + 2 < 48) {
            loadChunk(it + 2);
            asm volatile("cp.async.commit_group;" ::: "memory");
        }

        int buf = it % 3;
        uint32_t sa = sbase + (uint32_t)buf * 16384;
        uint32_t sb = sbase + 49152 + (uint32_t)buf * 16384;

#pragma unroll
        for (int ks = 0; ks < 4; ks++) {
            uint32_t a[4][4], b[4][4];
#pragma unroll
            for (int mt = 0; mt < 4; mt++) {
                uint32_t off = aRow + (uint32_t)(mt * 16 * 128) + (uint32_t)(ks * 32);
                ldmatrix_x4(a[mt], sa + SWZ(off));
            }
#pragma unroll
            for (int p = 0; p < 4; p++) {
                uint32_t off = bRow + (uint32_t)(p * 16 * 128) + (uint32_t)(ks * 32);
                ldmatrix_x4(b[p], sb + SWZ(off));
            }
#pragma unroll
            for (int mt = 0; mt < 4; mt++)
#pragma unroll
                for (int nt = 0; nt < 8; nt++)
                    mma16816(acc[mt][nt], a[mt],
                             b[nt >> 1][(nt & 1) * 2], b[nt >> 1][(nt & 1) * 2 + 1]);
        }
    }
}

// ---------------------------------------------------------------------------
__global__ void __launch_bounds__(128, 2) gemm_qkv(
    const __nv_bfloat16* __restrict__ Ahi, const __nv_bfloat16* __restrict__ Alo,
    const __nv_bfloat16* __restrict__ WhiB, const __nv_bfloat16* __restrict__ WloB,
    const float* __restrict__ bq, const float* __restrict__ bk,
    const float* __restrict__ bv,
    __nv_bfloat16* __restrict__ qhi, __nv_bfloat16* __restrict__ qlo,
    __nv_bfloat16* __restrict__ khi, __nv_bfloat16* __restrict__ klo,
    __nv_bfloat16* __restrict__ vhi, __nv_bfloat16* __restrict__ vlo)
{
    extern __shared__ __align__(1024) char smem[];
    const int z = blockIdx.z;
    const __nv_bfloat16* Bhi = WhiB + (size_t)z * HID * HID;
    const __nv_bfloat16* Blo = WloB + (size_t)z * HID * HID;
    const float* bias = (z == 0) ? bq : (z == 1) ? bk : bv;
    __nv_bfloat16* Chi = (z == 0) ? qhi : (z == 1) ? khi : vhi;
    __nv_bfloat16* Clo = (z == 0) ? qlo : (z == 1) ? klo : vlo;
    const float scale = (z == 0) ? SCALE : 1.0f;

    const int bm = blockIdx.y * 128, bn = blockIdx.x * 128;

    float acc[4][8][4];
#pragma unroll
    for (int i = 0; i < 4; i++)
#pragma unroll
        for (int j = 0; j < 8; j++)
#pragma unroll
            for (int k = 0; k < 4; k++) acc[i][j][k] = 0.f;

    gemm_core(Ahi, Alo, Bhi, Blo, bm, bn, smem_u32(smem), acc);

    const int tid = threadIdx.x, L = tid & 31, wid = tid >> 5;
    const int wm = wid >> 1, wn = wid & 1;
    const int r = L >> 2, c2 = (L & 3) * 2;
#pragma unroll
    for (int mt = 0; mt < 4; mt++) {
        int gm0 = bm + wm * 64 + mt * 16 + r;
#pragma unroll
        for (int nt = 0; nt < 8; nt++) {
            int gn = bn + wn * 64 + nt * 8 + c2;
            float b0 = bias[gn], b1 = bias[gn + 1];
            float v00 = (acc[mt][nt][0] + b0) * scale;
            float v01 = (acc[mt][nt][1] + b1) * scale;
            float v10 = (acc[mt][nt][2] + b0) * scale;
            float v11 = (acc[mt][nt][3] + b1) * scale;
            int hh = gn >> 6, d = gn & 63;
#pragma unroll
            for (int half = 0; half < 2; half++) {
                int gm = gm0 + half * 8;
                float x = half ? v10 : v00, y = half ? v11 : v01;
                int bb = gm >> 10, s = gm & 1023;
                size_t idx = ((size_t)((bb * NHEAD + hh) * SEQ) + s) * HDIM + d;
                __nv_bfloat162 hp = __floats2bfloat162_rn(x, y);
                float2 hf = __bfloat1622float2(hp);
                __nv_bfloat162 lp = __floats2bfloat162_rn(x - hf.x, y - hf.y);
                *(__nv_bfloat162*)(Chi + idx) = hp;
                *(__nv_bfloat162*)(Clo + idx) = lp;
            }
        }
    }
}

// ---------------------------------------------------------------------------
__global__ void __launch_bounds__(128, 2) gemm_out(
    const __nv_bfloat16* __restrict__ Ahi, const __nv_bfloat16* __restrict__ Alo,
    const __nv_bfloat16* __restrict__ Bhi, const __nv_bfloat16* __restrict__ Blo,
    const float* __restrict__ bias, float* __restrict__ C)
{
    extern __shared__ __align__(1024) char smem[];
    const int bm = blockIdx.y * 128, bn = blockIdx.x * 128;

    float acc[4][8][4];
#pragma unroll
    for (int i = 0; i < 4; i++)
#pragma unroll
        for (int j = 0; j < 8; j++)
#pragma unroll
            for (int k = 0; k < 4; k++) acc[i][j][k] = 0.f;

    gemm_core(Ahi, Alo, Bhi, Blo, bm, bn, smem_u32(smem), acc);

    const int tid = threadIdx.x, L = tid & 31, wid = tid >> 5;
    const int wm = wid >> 1, wn = wid & 1;
    const int r = L >> 2, c2 = (L & 3) * 2;
#pragma unroll
    for (int mt = 0; mt < 4; mt++) {
        int gm0 = bm + wm * 64 + mt * 16 + r;
#pragma unroll
        for (int nt = 0; nt < 8; nt++) {
            int gn = bn + wn * 64 + nt * 8 + c2;
            float b0 = bias[gn], b1 = bias[gn + 1];
            float2 w0, w1;
            w0.x = acc[mt][nt][0] + b0; w0.y = acc[mt][nt][1] + b1;
            w1.x = acc[mt][nt][2] + b0; w1.y = acc[mt][nt][3] + b1;
            *(float2*)(C + (size_t)gm0 * HID + gn) = w0;
            *(float2*)(C + (size_t)(gm0 + 8) * HID + gn) = w1;
        }
    }
}

// ---------------------------------------------------------------------------
// Tensor-core flash attention, bf16-split, double-buffered KV tiles.
// CTA = 128 q-rows x one (b,h); 4 warps x 32 q-rows; KV tile = 64.
// 6.0 MMA/ldsm: each K/V fragment feeds 2 m-tiles.
// ---------------------------------------------------------------------------
__global__ void __launch_bounds__(128) attn_mma(
    const __nv_bfloat16* __restrict__ Qhi, const __nv_bfloat16* __restrict__ Qlo,
    const __nv_bfloat16* __restrict__ Khi, const __nv_bfloat16* __restrict__ Klo,
    const __nv_bfloat16* __restrict__ Vhi, const __nv_bfloat16* __restrict__ Vlo,
    __nv_bfloat16* __restrict__ Chi, __nv_bfloat16* __restrict__ Clo)
{
    extern __shared__ __align__(1024) char smem[];   // 64 KB: buf0/buf1 32KB each
    __shared__ float sCB[2][64];

    const int tid = threadIdx.x, L = tid & 31, wid = tid >> 5;  // wid 0..3
    const int b = blockIdx.z, h = blockIdx.y;
    const int qcta = blockIdx.x * 128;
    const int q0w = qcta + wid * 32;
    const uint32_t sb = smem_u32(smem);
    const size_t headbase = ((size_t)(b * NHEAD + h)) * SEQ;

    // ---- stage Q tile (128x64 hi+lo) through buf0 into A-fragments ----
    {
        const __nv_bfloat16* qh = Qhi + (headbase + qcta) * HDIM;
        const __nv_bfloat16* ql = Qlo + (headbase + qcta) * HDIM;
#pragma unroll
        for (int i = 0; i < 8; i++) {
            int u = tid + i * 128;            // 0..1023 16B units
            int row = u >> 3, cu = u & 7;
            uint32_t sw = SWZ((uint32_t)(row * 128 + cu * 16));
            cp_async16(sb + sw, qh + (size_t)row * HDIM + cu * 8);
            cp_async16(sb + 16384 + sw, ql + (size_t)row * HDIM + cu * 8);
        }
        asm volatile("cp.async.commit_group;" ::: "memory");
        asm volatile("cp.async.wait_group 0;" ::: "memory");
        __syncthreads();
    }
    uint32_t qfh[2][4][4], qfl[2][4][4];
#pragma unroll
    for (int mi = 0; mi < 2; mi++) {
        uint32_t base = (uint32_t)((wid * 32 + mi * 16 + (L & 15)) * 128
                                   + ((L >> 4) << 4));
#pragma unroll
        for (int ks = 0; ks < 4; ks++) {
            uint32_t off = SWZ(base + ks * 32);
            ldmatrix_x4(qfh[mi][ks], sb + off);
            ldmatrix_x4(qfl[mi][ks], sb + 16384 + off);
        }
    }
    __syncthreads();   // Q fully consumed; buffers free for KV

    int nr[2][2];
#pragma unroll
    for (int mi = 0; mi < 2; mi++) {
        nr[mi][0] = g_nearest[b * SEQ + q0w + mi * 16 + (L >> 2)];
        nr[mi][1] = g_nearest[b * SEQ + q0w + mi * 16 + 8 + (L >> 2)];
    }

    float o[2][8][4];
#pragma unroll
    for (int mi = 0; mi < 2; mi++)
#pragma unroll
        for (int i = 0; i < 8; i++)
#pragma unroll
            for (int j = 0; j < 4; j++) o[mi][i][j] = 0.f;
    float mx[2][2] = {{-1e30f, -1e30f}, {-1e30f, -1e30f}};
    float ls[2][2] = {{0.f, 0.f}, {0.f, 0.f}};

    uint32_t kBase = (uint32_t)((L & 7) + ((L >> 4) & 1) * 8) * 128
                   + (((L >> 3) & 1) << 4);
    uint32_t vBase = (uint32_t)((L & 7) + ((L >> 3) & 1) * 8) * 128
                   + ((L >> 4) << 4);

    auto issueTile = [&](int t) {
        int buf = t & 1;
        uint32_t base = sb + buf * 32768;
        int kt = t * 64;
        const __nv_bfloat16* kh = Khi + (headbase + kt) * HDIM;
        const __nv_bfloat16* kl = Klo + (headbase + kt) * HDIM;
        const __nv_bfloat16* vh = Vhi + (headbase + kt) * HDIM;
        const __nv_bfloat16* vl = Vlo + (headbase + kt) * HDIM;
#pragma unroll
        for (int i = 0; i < 4; i++) {
            int u = tid + i * 128;            // 0..511 16B units per section
            int row = u >> 3, cu = u & 7;
            uint32_t sw = SWZ((uint32_t)(row * 128 + cu * 16));
            size_t g = (size_t)row * HDIM + cu * 8;
            cp_async16(base + sw,         kh + g);
            cp_async16(base +  8192 + sw, kl + g);
            cp_async16(base + 16384 + sw, vh + g);
            cp_async16(base + 24576 + sw, vl + g);
        }
        if (tid < 64) sCB[buf][tid] = g_colbias[b * SEQ + kt + tid];
        asm volatile("cp.async.commit_group;" ::: "memory");
    };

    issueTile(0);
    issueTile(1);

    for (int it = 0; it < 16; it++) {
        if (it + 1 < 16)
            asm volatile("cp.async.wait_group 1;" ::: "memory");
        else
            asm volatile("cp.async.wait_group 0;" ::: "memory");
        __syncthreads();

        const int buf = it & 1;
        const uint32_t base = sb + buf * 32768;
        const int kt = it * 64;

        // ---- S = Qh*Kh + Qh*Kl + Ql*Kh  (both m-tiles per K fragment) ----
        float s[2][8][4];
#pragma unroll
        for (int mi = 0; mi < 2; mi++)
#pragma unroll
            for (int i = 0; i < 8; i++)
#pragma unroll
                for (int j = 0; j < 4; j++) s[mi][i][j] = 0.f;

#pragma unroll
        for (int ks = 0; ks < 4; ks++) {
#pragma unroll
            for (int p = 0; p < 4; p++) {
                uint32_t off = SWZ(kBase + (uint32_t)(p * 16 * 128) + (uint32_t)(ks * 32));
                uint32_t f[4];
                ldmatrix_x4(f, base + off);                 // K hi
#pragma unroll
                for (int mi = 0; mi < 2; mi++) {
                    mma16816(s[mi][2*p],   qfh[mi][ks], f[0], f[1]);
                    mma16816(s[mi][2*p],   qfl[mi][ks], f[0], f[1]);
                    mma16816(s[mi][2*p+1], qfh[mi][ks], f[2], f[3]);
                    mma16816(s[mi][2*p+1], qfl[mi][ks], f[2], f[3]);
                }
                ldmatrix_x4(f, base + 8192 + off);          // K lo
#pragma unroll
                for (int mi = 0; mi < 2; mi++) {
                    mma16816(s[mi][2*p],   qfh[mi][ks], f[0], f[1]);
                    mma16816(s[mi][2*p+1], qfh[mi][ks], f[2], f[3]);
                }
            }
        }

        // ---- bias + online softmax (per m-tile) ----
        int colb = kt + 2 * (L & 3);
        float cb0[8], cb1[8];
#pragma unroll
        for (int nb = 0; nb < 8; nb++) {
            cb0[nb] = sCB[buf][nb * 8 + 2 * (L & 3)];
            cb1[nb] = sCB[buf][nb * 8 + 2 * (L & 3) + 1];
        }
#pragma unroll
        for (int mi = 0; mi < 2; mi++) {
            float t0 = -1e30f, t1 = -1e30f;
#pragma unroll
            for (int nb = 0; nb < 8; nb++) {
                int g0 = colb + nb * 8, g1 = g0 + 1;
                s[mi][nb][0] += cb0[nb] + (g0 == nr[mi][0] ? 2.f : 0.f);
                s[mi][nb][1] += cb1[nb] + (g1 == nr[mi][0] ? 2.f : 0.f);
                s[mi][nb][2] += cb0[nb] + (g0 == nr[mi][1] ? 2.f : 0.f);
                s[mi][nb][3] += cb1[nb] + (g1 == nr[mi][1] ? 2.f : 0.f);
                t0 = fmaxf(t0, fmaxf(s[mi][nb][0], s[mi][nb][1]));
                t1 = fmaxf(t1, fmaxf(s[mi][nb][2], s[mi][nb][3]));
            }
            t0 = fmaxf(t0, __shfl_xor_sync(0xffffffffu, t0, 1));
            t0 = fmaxf(t0, __shfl_xor_sync(0xffffffffu, t0, 2));
            t1 = fmaxf(t1, __shfl_xor_sync(0xffffffffu, t1, 1));
            t1 = fmaxf(t1, __shfl_xor_sync(0xffffffffu, t1, 2));
            float nm0 = fmaxf(mx[mi][0], t0), nm1 = fmaxf(mx[mi][1], t1);
            float cr0 = __expf(mx[mi][0] - nm0), cr1 = __expf(mx[mi][1] - nm1);
            mx[mi][0] = nm0; mx[mi][1] = nm1;
            ls[mi][0] *= cr0; ls[mi][1] *= cr1;
#pragma unroll
            for (int nb = 0; nb < 8; nb++) {
                o[mi][nb][0] *= cr0; o[mi][nb][1] *= cr0;
                o[mi][nb][2] *= cr1; o[mi][nb][3] *= cr1;
                s[mi][nb][0] = __expf(s[mi][nb][0] - nm0); ls[mi][0] += s[mi][nb][0];
                s[mi][nb][1] = __expf(s[mi][nb][1] - nm0); ls[mi][0] += s[mi][nb][1];
                s[mi][nb][2] = __expf(s[mi][nb][2] - nm1); ls[mi][1] += s[mi][nb][2];
                s[mi][nb][3] = __expf(s[mi][nb][3] - nm1); ls[mi][1] += s[mi][nb][3];
            }
        }

        // ---- O += Ph*Vh + Ph*Vl + Pl*Vh  (both m-tiles per V fragment) ----
#pragma unroll
        for (int ks = 0; ks < 4; ks++) {
            uint32_t ah[2][4], al[2][4];
#pragma unroll
            for (int mi = 0; mi < 2; mi++) {
#pragma unroll
                for (int half = 0; half < 2; half++) {
                    int nb = 2 * ks + half;
                    __nv_bfloat162 h01 = __floats2bfloat162_rn(s[mi][nb][0], s[mi][nb][1]);
                    __nv_bfloat162 h23 = __floats2bfloat162_rn(s[mi][nb][2], s[mi][nb][3]);
                    float2 f01 = __bfloat1622float2(h01);
                    float2 f23 = __bfloat1622float2(h23);
                    ah[mi][2*half]   = *(uint32_t*)&h01;
                    ah[mi][2*half+1] = *(uint32_t*)&h23;
                    al[mi][2*half]   = pack_bf2(s[mi][nb][0] - f01.x, s[mi][nb][1] - f01.y);
                    al[mi][2*half+1] = pack_bf2(s[mi][nb][2] - f23.x, s[mi][nb][3] - f23.y);
                }
            }
#pragma unroll
            for (int p = 0; p < 4; p++) {
                uint32_t off = SWZ(vBase + (uint32_t)(ks * 16 * 128) + (uint32_t)(p * 32));
                uint32_t f[4];
                ldmatrix_x4_t(f, base + 16384 + off);       // V hi
#pragma unroll
                for (int mi = 0; mi < 2; mi++) {
                    mma16816(o[mi][2*p],   ah[mi], f[0], f[1]);
                    mma16816(o[mi][2*p],   al[mi], f[0], f[1]);
                    mma16816(o[mi][2*p+1], ah[mi], f[2], f[3]);
                    mma16816(o[mi][2*p+1], al[mi], f[2], f[3]);
                }
                ldmatrix_x4_t(f, base + 24576 + off);       // V lo
#pragma unroll
                for (int mi = 0; mi < 2; mi++) {
                    mma16816(o[mi][2*p],   ah[mi], f[0], f[1]);
                    mma16816(o[mi][2*p+1], ah[mi], f[2], f[3]);
                }
            }
        }

        __syncthreads();                 // all warps done with buf
        if (it + 2 < 16) issueTile(it + 2);
    }

    // ---- finalize ----
#pragma unroll
    for (int mi = 0; mi < 2; mi++) {
        float l0 = ls[mi][0], l1 = ls[mi][1];
        l0 += __shfl_xor_sync(0xffffffffu, l0, 1);
        l0 += __shfl_xor_sync(0xffffffffu, l0, 2);
        l1 += __shfl_xor_sync(0xffffffffu, l1, 1);
        l1 += __shfl_xor_sync(0xffffffffu, l1, 2);
        float inv0 = 1.f / l0, inv1 = 1.f / l1;

        int r0g = q0w + mi * 16 + (L >> 2), r1g = r0g + 8;
        size_t base0 = (size_t)(b * SEQ + r0g) * HID + h * HDIM + 2 * (L & 3);
        size_t base1 = (size_t)(b * SEQ + r1g) * HID + h * HDIM + 2 * (L & 3);
#pragma unroll
        for (int nb = 0; nb < 8; nb++) {
            float x0 = o[mi][nb][0] * inv0, y0 = o[mi][nb][1] * inv0;
            float x1 = o[mi][nb][2] * inv1, y1 = o[mi][nb][3] * inv1;
            __nv_bfloat162 hp0 = __floats2bfloat162_rn(x0, y0);
            __nv_bfloat162 hp1 = __floats2bfloat162_rn(x1, y1);
            float2 hf0 = __bfloat1622float2(hp0);
            float2 hf1 = __bfloat1622float2(hp1);
            __nv_bfloat162 lp0 = __floats2bfloat162_rn(x0 - hf0.x, y0 - hf0.y);
            __nv_bfloat162 lp1 = __floats2bfloat162_rn(x1 - hf1.x, y1 - hf1.y);
            *(__nv_bfloat162*)(Chi + base0 + nb * 8) = hp0;
            *(__nv_bfloat162*)(Clo + base0 + nb * 8) = lp0;
            *(__nv_bfloat162*)(Chi + base1 + nb * 8) = hp1;
            *(__nv_bfloat162*)(Clo + base1 + nb * 8) = lp1;
        }
    }
}

// ---------------------------------------------------------------------------
extern "C" void kernel_launch(void* const* d_in, const int* in_sizes, int n_in,
                              void* d_out, int out_size)
{
    const float* hs     = (const float*)d_in[0];
    const int*   morpho = (const int*)  d_in[1];
    const float* Wq = (const float*)d_in[2];
    const float* bq = (const float*)d_in[3];
    const float* Wk = (const float*)d_in[4];
    const float* bk = (const float*)d_in[5];
    const float* Wv = (const float*)d_in[6];
    const float* bv = (const float*)d_in[7];
    const float* Wo = (const float*)d_in[8];
    const float* bo = (const float*)d_in[9];
    float* out = (float*)d_out;

    __nv_bfloat16 *ahi, *alo, *whi, *wlo;
    __nv_bfloat16 *qhi, *qlo, *khi, *klo, *vhi, *vlo;
    cudaGetSymbolAddress((void**)&ahi, g_Ahi);
    cudaGetSymbolAddress((void**)&alo, g_Alo);
    cudaGetSymbolAddress((void**)&whi, g_Whi);
    cudaGetSymbolAddress((void**)&wlo, g_Wlo);
    cudaGetSymbolAddress((void**)&qhi, g_Qhi);
    cudaGetSymbolAddress((void**)&qlo, g_Qlo);
    cudaGetSymbolAddress((void**)&khi, g_Khi);
    cudaGetSymbolAddress((void**)&klo, g_Klo);
    cudaGetSymbolAddress((void**)&vhi, g_Vhi);
    cudaGetSymbolAddress((void**)&vlo, g_Vlo);

    static bool attr_set = false;
    if (!attr_set) {
        cudaFuncSetAttribute(gemm_qkv,
                             cudaFuncAttributeMaxDynamicSharedMemorySize, 98304);
        cudaFuncSetAttribute(gemm_out,
                             cudaFuncAttributeMaxDynamicSharedMemorySize, 98304);
        cudaFuncSetAttribute(attn_mma,
                             cudaFuncAttributeMaxDynamicSharedMemorySize, 65536);
        attr_set = true;
    }

    bias_kernel<<<dim3(BATCH, SEQ/128), 128>>>(morpho);

    split_kernel<<<MTOT*HID/1024, 256>>>((const float4*)hs,
                                         (__nv_bfloat162*)ahi, (__nv_bfloat162*)alo);

    wtrans_kernel<<<dim3(HID/32, HID/32, 4), dim3(32, 8)>>>(
        Wq, Wk, Wv, Wo, whi, wlo);

    gemm_qkv<<<dim3(HID/128, MTOT/128, 3), 128, 98304>>>(
        ahi, alo, whi, wlo, bq, bk, bv, qhi, qlo, khi, klo, vhi, vlo);

    attn_mma<<<dim3(SEQ/128, NHEAD, BATCH), 128, 65536>>>(
        qhi, qlo, khi, klo, vhi, vlo, ahi, alo);

    gemm_out<<<dim3(HID/128, MTOT/128), 128, 98304>>>(
        ahi, alo, whi + 3*(size_t)HID*HID, wlo + 3*(size_t)HID*HID, bo, out);
}